// round 2
// baseline (speedup 1.0000x reference)
#include <cuda_runtime.h>
#include <math.h>

// Problem constants
#define Bn 128
#define Tn 512
#define In 128
#define Hn 1024
#define Gn 4096      // 4*H
#define KHn 1024
#define KCATn 1152   // H + I
#define BHn (Bn * Hn)

// ---------------------------------------------------------------------------
// Device scratch (static; allocation-free per harness rules)
// ---------------------------------------------------------------------------
__device__ float g_wcat_enc[Gn * KCATn];       // [enc_Whh | enc_Wih], row-major, ld=1152
__device__ float g_wcat_dec[Gn * KCATn];       // [dec_Whh | dec_Wih]
__device__ float g_wsum_dec[Gn * KHn];         // dec_Whh + dec_Wih @ lin_W
__device__ float g_benc[Gn];                   // enc_bih + enc_bhh
__device__ float g_bdec[Gn];                   // dec_bih + dec_bhh
__device__ float g_b2dec[Gn];                  // dec_b + dec_Wih @ lin_b
__device__ float g_h[2 * BHn];                 // encoder h ping-pong
__device__ float g_c[BHn];                     // cell state (in-place, shared enc->dec)
__device__ float g_dech[Tn * BHn];             // decoder h history [s][b][h]
__device__ unsigned int g_arrive;              // grid barrier counter

__device__ __forceinline__ float sigf(float x) { return 1.0f / (1.0f + __expf(-x)); }

// ---------------------------------------------------------------------------
// Prep kernels (inside the captured graph; weights are harness inputs)
// ---------------------------------------------------------------------------
__global__ void zero_state_kernel() {
    int i = blockIdx.x * blockDim.x + threadIdx.x;
    if (i == 0) g_arrive = 0u;
    if (i < BHn) { g_h[i] = 0.0f; g_c[i] = 0.0f; }
}

__global__ void build_wcat_kernel(const float* __restrict__ Whh,
                                  const float* __restrict__ Wih,
                                  int which /*0=enc,1=dec*/) {
    int i = blockIdx.x * blockDim.x + threadIdx.x;
    if (i < Gn * KCATn) {
        int n = i / KCATn;
        int k = i - n * KCATn;
        float v = (k < KHn) ? Whh[n * KHn + k] : Wih[n * In + (k - KHn)];
        if (which == 0) g_wcat_enc[i] = v; else g_wcat_dec[i] = v;
    }
}

// g_wsum_dec[n][k] = dec_Whh[n][k] + sum_j dec_Wih[n][j] * lin_W[j][k]
__global__ __launch_bounds__(256) void build_wsum_kernel(
    const float* __restrict__ Whh, const float* __restrict__ Wih,
    const float* __restrict__ linW) {
    const int n = blockIdx.x;            // 0..4095
    __shared__ float wr[In];
    if (threadIdx.x < In) wr[threadIdx.x] = Wih[n * In + threadIdx.x];
    __syncthreads();
    #pragma unroll
    for (int c = 0; c < 4; c++) {
        int k = threadIdx.x + 256 * c;   // 0..1023
        float s = 0.0f;
        #pragma unroll 8
        for (int j = 0; j < In; j++) s = fmaf(wr[j], linW[j * Hn + k], s);
        g_wsum_dec[n * KHn + k] = Whh[n * KHn + k] + s;
    }
}

__global__ void build_bias_kernel(const float* __restrict__ ebih, const float* __restrict__ ebhh,
                                  const float* __restrict__ dbih, const float* __restrict__ dbhh,
                                  const float* __restrict__ dWih, const float* __restrict__ linb) {
    int n = blockIdx.x * blockDim.x + threadIdx.x;
    if (n < Gn) {
        g_benc[n] = ebih[n] + ebhh[n];
        float bd = dbih[n] + dbhh[n];
        g_bdec[n] = bd;
        float s = 0.0f;
        #pragma unroll 8
        for (int j = 0; j < In; j++) s = fmaf(dWih[n * In + j], linb[j], s);
        g_b2dec[n] = bd + s;
    }
}

// ---------------------------------------------------------------------------
// Persistent kernel: runs all 512 encoder + 512 decoder steps with a global
// software barrier between steps. 128 blocks (< 148 SMs: co-residency
// guaranteed), 256 threads.
// Per step: fused GEMM [128, K] x W[4096, K]^T + LSTM gate epilogue.
// Block tile: 64 batch rows x 16 hidden units x 4 gates.
// ---------------------------------------------------------------------------
__global__ __launch_bounds__(256, 1) void lstm_persist_kernel(
    const float* __restrict__ x_input,
    const int* __restrict__ lengths,
    const int* __restrict__ tf_mask,
    float* __restrict__ enc_out) {
    const int tid = threadIdx.x;
    const int tx = tid & 15;                 // unit within tile
    const int ty = tid >> 4;                 // batch row group
    const int u0 = (blockIdx.x & 63) << 4;   // unit tile start (64 tiles)
    const int m0 = (blockIdx.x >> 6) << 6;   // batch tile start (2 tiles)

    __shared__ __align__(16) float As[16][72];  // [k][m], pad -> conflict-free
    __shared__ __align__(16) float Ws[16][72];  // [k][ci]

    const int lrow = tid >> 2;  // 0..63 : smem column index this thread fills
    const int lc4  = tid & 3;   // which float4 of the 16-wide k chunk
    // W row for smem column lrow: unit-major ordering (unit = lrow/4, gate = lrow%4)
    const int wrow = (lrow & 3) * Hn + u0 + (lrow >> 2);
    const int am = m0 + lrow;
    const int u = u0 + tx;

    for (int it = 0; it < 2 * Tn; it++) {
        const int mode = (it >= Tn);
        const int step = mode ? (it - Tn) : it;

        const float* h_in;
        float* h_out;
        const float* W;
        const float* bias;
        int K, ts;

        if (!mode) {
            h_in  = g_h + (step & 1) * BHn;
            h_out = g_h + ((step + 1) & 1) * BHn;
            W = g_wcat_enc; bias = g_benc; K = KCATn; ts = step;
        } else {
            h_in  = (step == 0) ? g_h : (g_dech + (size_t)(step - 1) * BHn);
            h_out = g_dech + (size_t)step * BHn;
            int teach;
            if (step == 0) { teach = 1; ts = Tn - 1; }
            else           { teach = tf_mask[step - 1]; ts = step - 1; }
            if (teach) { W = g_wcat_dec; bias = g_bdec;  K = KCATn; }
            else       { W = g_wsum_dec; bias = g_b2dec; K = KHn;   }
        }

        const float* wptr  = W + (size_t)wrow * K;
        const float* aptrh = h_in + (size_t)am * Hn;
        const float* aptrx = x_input + ((size_t)am * Tn + ts) * In - KHn;

        float acc[4][4] = {};

        for (int k0 = 0; k0 < K; k0 += 16) {
            const int k = k0 + lc4 * 4;
            float4 wv = *(const float4*)(wptr + k);
            float4 av = (k < KHn) ? *(const float4*)(aptrh + k)
                                  : *(const float4*)(aptrx + k);
            __syncthreads();
            Ws[lc4 * 4 + 0][lrow] = wv.x; Ws[lc4 * 4 + 1][lrow] = wv.y;
            Ws[lc4 * 4 + 2][lrow] = wv.z; Ws[lc4 * 4 + 3][lrow] = wv.w;
            As[lc4 * 4 + 0][lrow] = av.x; As[lc4 * 4 + 1][lrow] = av.y;
            As[lc4 * 4 + 2][lrow] = av.z; As[lc4 * 4 + 3][lrow] = av.w;
            __syncthreads();
            #pragma unroll
            for (int kk = 0; kk < 16; kk++) {
                float4 a4 = *(const float4*)&As[kk][ty * 4];
                float4 w4 = *(const float4*)&Ws[kk][tx * 4];
                float a[4] = {a4.x, a4.y, a4.z, a4.w};
                float w[4] = {w4.x, w4.y, w4.z, w4.w};
                #pragma unroll
                for (int i = 0; i < 4; i++)
                    #pragma unroll
                    for (int j = 0; j < 4; j++)
                        acc[i][j] = fmaf(a[i], w[j], acc[i][j]);
            }
        }

        // Epilogue: gates -> LSTM cell update
        const float bi = bias[u];
        const float bf = bias[Hn + u];
        const float bg = bias[2 * Hn + u];
        const float bo = bias[3 * Hn + u];
        #pragma unroll
        for (int r = 0; r < 4; r++) {
            const int m = m0 + ty * 4 + r;
            const size_t idx = (size_t)m * Hn + u;
            float iv = sigf(acc[r][0] + bi);
            float fv = sigf(acc[r][1] + bf);
            float gv = tanhf(acc[r][2] + bg);
            float ov = sigf(acc[r][3] + bo);
            float cold = g_c[idx];
            float c2 = fmaf(fv, cold, iv * gv);
            float h2 = ov * tanhf(c2);
            if (!mode) {
                bool valid = step < lengths[m];
                h_out[idx] = valid ? h2 : h_in[idx];
                g_c[idx]   = valid ? c2 : cold;
                enc_out[((size_t)m * Tn + step) * Hn + u] = valid ? h2 : 0.0f;
            } else {
                h_out[idx] = h2;
                g_c[idx]   = c2;
            }
        }

        // ---- grid-wide barrier (arrive: atomic, poll: volatile load) ----
        __syncthreads();
        if (tid == 0) {
            __threadfence();                       // order writes + CCTL.IVALL
            atomicAdd(&g_arrive, 1u);
            const unsigned goal = (unsigned)(it + 1) * gridDim.x;
            while (*((volatile unsigned*)&g_arrive) < goal) {}
            __threadfence();                       // invalidate stale L1 lines
        }
        __syncthreads();
    }
}

// ---------------------------------------------------------------------------
// Final output projection: outputs[b][s][:] = dec_h[s][b][:] @ lin_W^T + lin_b
// M = T*B = 65536 rows (r = s*B + b), N = 128, K = 1024.
// ---------------------------------------------------------------------------
__global__ __launch_bounds__(256, 1) void final_gemm_kernel(
    const float* __restrict__ linW, const float* __restrict__ linb,
    float* __restrict__ out) {
    const int tid = threadIdx.x;
    const int tx = tid & 15, ty = tid >> 4;
    const int r0 = blockIdx.x << 6;
    const int n0 = blockIdx.y << 6;

    __shared__ __align__(16) float As[16][72];
    __shared__ __align__(16) float Ws[16][72];
    float acc[4][4] = {};

    const int lrow = tid >> 2, lc4 = tid & 3;
    const float* aptr = g_dech + (size_t)(r0 + lrow) * Hn;
    const float* wptr = linW + (size_t)(n0 + lrow) * Hn;

    for (int k0 = 0; k0 < Hn; k0 += 16) {
        const int k = k0 + lc4 * 4;
        float4 wv = *(const float4*)(wptr + k);
        float4 av = *(const float4*)(aptr + k);
        __syncthreads();
        Ws[lc4 * 4 + 0][lrow] = wv.x; Ws[lc4 * 4 + 1][lrow] = wv.y;
        Ws[lc4 * 4 + 2][lrow] = wv.z; Ws[lc4 * 4 + 3][lrow] = wv.w;
        As[lc4 * 4 + 0][lrow] = av.x; As[lc4 * 4 + 1][lrow] = av.y;
        As[lc4 * 4 + 2][lrow] = av.z; As[lc4 * 4 + 3][lrow] = av.w;
        __syncthreads();
        #pragma unroll
        for (int kk = 0; kk < 16; kk++) {
            float4 a4 = *(const float4*)&As[kk][ty * 4];
            float4 w4 = *(const float4*)&Ws[kk][tx * 4];
            float a[4] = {a4.x, a4.y, a4.z, a4.w};
            float w[4] = {w4.x, w4.y, w4.z, w4.w};
            #pragma unroll
            for (int i = 0; i < 4; i++)
                #pragma unroll
                for (int j = 0; j < 4; j++)
                    acc[i][j] = fmaf(a[i], w[j], acc[i][j]);
        }
    }

    #pragma unroll
    for (int r = 0; r < 4; r++) {
        int rr = r0 + ty * 4 + r;
        int s = rr >> 7;     // / B
        int b = rr & 127;    // % B
        int n = n0 + tx * 4;
        float4 o;
        o.x = acc[r][0] + linb[n + 0];
        o.y = acc[r][1] + linb[n + 1];
        o.z = acc[r][2] + linb[n + 2];
        o.w = acc[r][3] + linb[n + 3];
        *(float4*)(out + ((size_t)b * Tn + s) * In + n) = o;
    }
}

// ---------------------------------------------------------------------------
// kernel_launch: 7 graph nodes total (avoids the multi-MB graph upload buffer
// that a 1029-node graph left resident after teardown).
// Inputs: x_input, enc_Wih, enc_Whh, enc_bih, enc_bhh, dec_Wih, dec_Whh,
// dec_bih, dec_bhh, lin_W, lin_b, lengths, tf_mask.
// Output: [outputs (B*T*I) | encoder_output (B*T*H)] float32.
// ---------------------------------------------------------------------------
extern "C" void kernel_launch(void* const* d_in, const int* in_sizes, int n_in,
                              void* d_out, int out_size) {
    const float* x       = (const float*)d_in[0];
    const float* eWih    = (const float*)d_in[1];
    const float* eWhh    = (const float*)d_in[2];
    const float* ebih    = (const float*)d_in[3];
    const float* ebhh    = (const float*)d_in[4];
    const float* dWih    = (const float*)d_in[5];
    const float* dWhh    = (const float*)d_in[6];
    const float* dbih    = (const float*)d_in[7];
    const float* dbhh    = (const float*)d_in[8];
    const float* linW    = (const float*)d_in[9];
    const float* linb    = (const float*)d_in[10];
    const int*   lengths = (const int*)d_in[11];
    const int*   tfm     = (const int*)d_in[12];
    float* out = (float*)d_out;
    float* enc_out = out + (size_t)Bn * Tn * In;

    zero_state_kernel<<<(BHn + 255) / 256, 256>>>();
    build_wcat_kernel<<<(Gn * KCATn + 255) / 256, 256>>>(eWhh, eWih, 0);
    build_wcat_kernel<<<(Gn * KCATn + 255) / 256, 256>>>(dWhh, dWih, 1);
    build_wsum_kernel<<<Gn, 256>>>(dWhh, dWih, linW);
    build_bias_kernel<<<(Gn + 255) / 256, 256>>>(ebih, ebhh, dbih, dbhh, dWih, linb);

    // Entire encoder + decoder recurrence in ONE persistent launch
    lstm_persist_kernel<<<128, 256>>>(x, lengths, tfm, enc_out);

    // All decoder outputs in one parallel GEMM
    final_gemm_kernel<<<dim3((Tn * Bn) / 64, In / 64), 256>>>(linW, linb, out);
}

// round 7
// speedup vs baseline: 1.7280x; 1.7280x over previous
#include <cuda_runtime.h>
#include <cuda_bf16.h>
#include <math.h>
#include <stdint.h>
#include <mma.h>
using namespace nvcuda;

#define Bn 128
#define Tn 512
#define In 128
#define Hn 1024
#define Gn 4096
#define KHn 1024
#define KCAT 1152
#define BHn (Bn*Hn)

typedef __nv_bfloat16 bf16;

// ---------------------------------------------------------------------------
// Static device scratch — plain row-major bf16 hi/lo planes
// NOTE: every reference to these symbols happens in DEVICE code. Passing a
// __device__ symbol as a host-side kernel argument silently yields the host
// shadow address (and on GB300, ATS makes the resulting writes land in host
// memory without trapping) — that was the round-3/4/6 bug.
// ---------------------------------------------------------------------------
__device__ bf16 g_WencH[(size_t)Gn*KCAT], g_WencL[(size_t)Gn*KCAT];
__device__ bf16 g_WdecH[(size_t)Gn*KCAT], g_WdecL[(size_t)Gn*KCAT];
__device__ bf16 g_WsumH[(size_t)Gn*KHn],  g_WsumL[(size_t)Gn*KHn];
__device__ float g_wsum[(size_t)Gn*KHn];
__device__ bf16 g_xH[(size_t)Tn*Bn*In], g_xL[(size_t)Tn*Bn*In];  // [t][m][k]
__device__ bf16 g_hH[2][BHn], g_hL[2][BHn];                       // [m][h]
__device__ float g_hF[2][BHn];
__device__ float g_c[BHn];
__device__ float g_dech[(size_t)Tn*BHn];                          // [s][b][h]
__device__ float g_benc[Gn], g_bdec[Gn], g_b2dec[Gn];
__device__ unsigned g_arrive;

__device__ __forceinline__ float sigf(float x){ return 1.f/(1.f+__expf(-x)); }

// ---------------------------------------------------------------------------
// Prep kernels (elementwise; all __device__ symbols referenced in device code)
// ---------------------------------------------------------------------------
__global__ void zero_state_kernel(){
    int i = blockIdx.x*blockDim.x + threadIdx.x;
    if (i == 0) g_arrive = 0u;
    if (i < BHn){
        g_hH[0][i] = __float2bfloat16(0.f);
        g_hL[0][i] = __float2bfloat16(0.f);
        g_hF[0][i] = 0.f;
        g_c[i] = 0.f;
    }
}

// which: 0 -> enc (src harness Whh/Wih, K=KCAT, dst g_Wenc*)
//        1 -> dec (src harness Whh/Wih, K=KCAT, dst g_Wdec*)
//        2 -> sum (src g_wsum device symbol, K=KHn, dst g_Wsum*)
// dst[n][k] planes; packed col n -> unit n>>2, gate n&3 (src row = gate*H + unit)
__global__ void pack_wplanes_kernel(const float* __restrict__ Whh,
                                    const float* __restrict__ Wih,
                                    int which, int K){
    size_t idx = (size_t)blockIdx.x*256 + threadIdx.x;
    if (idx >= (size_t)Gn*K) return;
    int n = (int)(idx / K), k = (int)(idx - (size_t)n*K);
    int srcrow = (n & 3)*Hn + (n >> 2);
    float v;
    if (which == 2)
        v = g_wsum[(size_t)srcrow*KHn + k];
    else
        v = (k < KHn) ? Whh[(size_t)srcrow*KHn + k] : Wih[(size_t)srcrow*In + (k - KHn)];
    bf16* hiP = (which == 0) ? g_WencH : (which == 1) ? g_WdecH : g_WsumH;
    bf16* loP = (which == 0) ? g_WencL : (which == 1) ? g_WdecL : g_WsumL;
    bf16 hi = __float2bfloat16(v);
    hiP[idx] = hi;
    loP[idx] = __float2bfloat16(v - __bfloat162float(hi));
}

// x planes: [t][m][k]
__global__ void pack_x_kernel(const float* __restrict__ x){
    size_t idx = (size_t)blockIdx.x*256 + threadIdx.x;
    if (idx >= (size_t)Tn*Bn*In) return;
    int k = (int)(idx & (In - 1));
    int m = (int)((idx >> 7) & (Bn - 1));
    int t = (int)(idx >> 14);
    float v = x[((size_t)m*Tn + t)*In + k];
    bf16 hi = __float2bfloat16(v);
    g_xH[idx] = hi;
    g_xL[idx] = __float2bfloat16(v - __bfloat162float(hi));
}

// g_wsum[n][k] = dec_Whh[n][k] + sum_j dec_Wih[n][j] * lin_W[j][k]
__global__ __launch_bounds__(256) void build_wsum_kernel(
    const float* __restrict__ Whh, const float* __restrict__ Wih,
    const float* __restrict__ linW){
    const int n = blockIdx.x;
    __shared__ float wr[In];
    if (threadIdx.x < In) wr[threadIdx.x] = Wih[n*In + threadIdx.x];
    __syncthreads();
    #pragma unroll
    for (int c = 0; c < 4; c++){
        int k = threadIdx.x + 256*c;
        float s = 0.0f;
        #pragma unroll 8
        for (int j = 0; j < In; j++) s = fmaf(wr[j], linW[j*Hn + k], s);
        g_wsum[(size_t)n*KHn + k] = Whh[(size_t)n*KHn + k] + s;
    }
}

__global__ void build_bias_kernel(const float* __restrict__ ebih, const float* __restrict__ ebhh,
                                  const float* __restrict__ dbih, const float* __restrict__ dbhh,
                                  const float* __restrict__ dWih, const float* __restrict__ linb){
    int n = blockIdx.x*blockDim.x + threadIdx.x;
    if (n < Gn){
        g_benc[n] = ebih[n] + ebhh[n];
        float bd = dbih[n] + dbhh[n];
        g_bdec[n] = bd;
        float s = 0.0f;
        #pragma unroll 8
        for (int j = 0; j < In; j++) s = fmaf(dWih[n*In + j], linb[j], s);
        g_b2dec[n] = bd + s;
    }
}

// ---------------------------------------------------------------------------
// Persistent recurrence: 4-term BF16 wmma (m16n16k16), plain smem layouts.
// 128 blocks x 256 threads; block tile 64(M) x 64(N); warp tile 16x32.
// Per BK=32 stage: LDG.128 prefetch -> STS -> wmma. Single-buffered.
// ---------------------------------------------------------------------------
__global__ __launch_bounds__(256, 1) void lstm_persist_kernel(
    const int* __restrict__ lengths, const int* __restrict__ tf_mask,
    float* __restrict__ enc_out){
    __shared__ union { bf16 a[2][64][40]; float d[64][68]; } SA;
    __shared__ bf16 SW[2][64][40];
    const int tid = threadIdx.x, wid = tid >> 5;
    const int wm = wid & 3, wn = wid >> 2;       // warp: rows wm*16, cols wn*32
    const int mt = blockIdx.x >> 6, nt = blockIdx.x & 63;

    for (int it = 0; it < 2*Tn; it++){
        const int mode = it >= Tn;
        const int step = mode ? it - Tn : it;
        const int pin = it & 1, pout = pin ^ 1;

        const bf16 *WH, *WL; const float* bias; int K, ts;
        if (!mode){ WH = g_WencH; WL = g_WencL; bias = g_benc; K = KCAT; ts = step; }
        else {
            int teach;
            if (step == 0){ teach = 1; ts = Tn - 1; }
            else          { teach = tf_mask[step - 1]; ts = step - 1; }
            if (teach){ WH = g_WdecH; WL = g_WdecL; bias = g_bdec;  K = KCAT; }
            else      { WH = g_WsumH; WL = g_WsumL; bias = g_b2dec; K = KHn;  }
        }
        const int nst = K >> 5;
        const bf16* hHp = g_hH[pin];
        const bf16* hLp = g_hL[pin];

        wmma::fragment<wmma::accumulator,16,16,16,float> acc[2];
        wmma::fill_fragment(acc[0], 0.0f);
        wmma::fill_fragment(acc[1], 0.0f);

        uint4 pf[4];
        auto fetch = [&](int s){
            const int k0 = s << 5;
            #pragma unroll
            for (int i = 0; i < 4; i++){
                int c = tid + (i << 8);          // 0..1023
                const bf16* p;
                if (c < 512){                    // A chunks
                    int row = c >> 3, pl = (c >> 2) & 1, q = c & 3;
                    int k = k0 + (q << 3);
                    if (k < KHn) p = (pl ? hLp : hHp) + (size_t)(mt*64 + row)*KHn + k;
                    else         p = (pl ? g_xL : g_xH) + ((size_t)ts*Bn + mt*64 + row)*In + (k - KHn);
                } else {                         // W chunks
                    int c2 = c - 512;
                    int row = c2 >> 3, pl = (c2 >> 2) & 1, q = c2 & 3;
                    int k = k0 + (q << 3);
                    p = (pl ? WL : WH) + (size_t)(nt*64 + row)*K + k;
                }
                pf[i] = *(const uint4*)p;
            }
        };

        fetch(0);
        for (int s = 0; s < nst; s++){
            __syncthreads();                     // prev compute / D reads done
            #pragma unroll
            for (int i = 0; i < 4; i++){
                int c = tid + (i << 8);
                if (c < 512){
                    int row = c >> 3, pl = (c >> 2) & 1, q = c & 3;
                    *(uint4*)&SA.a[pl][row][q << 3] = pf[i];
                } else {
                    int c2 = c - 512;
                    int row = c2 >> 3, pl = (c2 >> 2) & 1, q = c2 & 3;
                    *(uint4*)&SW[pl][row][q << 3] = pf[i];
                }
            }
            if (s + 1 < nst) fetch(s + 1);       // overlap next LDG with compute
            __syncthreads();
            #pragma unroll
            for (int kcl = 0; kcl < 2; kcl++){
                wmma::fragment<wmma::matrix_a,16,16,16,bf16,wmma::row_major> aH, aL;
                wmma::fragment<wmma::matrix_b,16,16,16,bf16,wmma::col_major> bH[2], bL[2];
                wmma::load_matrix_sync(aH, &SA.a[0][wm*16][kcl*16], 40);
                wmma::load_matrix_sync(aL, &SA.a[1][wm*16][kcl*16], 40);
                #pragma unroll
                for (int nf = 0; nf < 2; nf++){
                    wmma::load_matrix_sync(bH[nf], &SW[0][wn*32 + nf*16][kcl*16], 40);
                    wmma::load_matrix_sync(bL[nf], &SW[1][wn*32 + nf*16][kcl*16], 40);
                }
                #pragma unroll
                for (int nf = 0; nf < 2; nf++){
                    wmma::mma_sync(acc[nf], aH, bH[nf], acc[nf]);
                    wmma::mma_sync(acc[nf], aH, bL[nf], acc[nf]);
                    wmma::mma_sync(acc[nf], aL, bH[nf], acc[nf]);
                    wmma::mma_sync(acc[nf], aL, bL[nf], acc[nf]);
                }
            }
        }

        __syncthreads();                         // all frag loads done before D overwrite
        wmma::store_matrix_sync(&SA.d[wm*16][wn*32 +  0], acc[0], 68, wmma::mem_row_major);
        wmma::store_matrix_sync(&SA.d[wm*16][wn*32 + 16], acc[1], 68, wmma::mem_row_major);
        __syncthreads();

        // ---- layout-free epilogue: each thread = 1 batch row x 4 units ----
        {
            const int ml = tid >> 2;
            const int m  = mt*64 + ml;
            const bool valid = mode ? true : (step < lengths[m]);
            #pragma unroll
            for (int j = 0; j < 4; j++){
                const int ul = (tid & 3)*4 + j;
                const int u  = nt*16 + ul;
                float4 gv = *(const float4*)&SA.d[ml][ul*4];   // i,f,g,o
                float iv = sigf(gv.x + bias[u]);
                float fv = sigf(gv.y + bias[Hn + u]);
                float gg = tanhf(gv.z + bias[2*Hn + u]);
                float ov = sigf(gv.w + bias[3*Hn + u]);
                const size_t idx = (size_t)m*Hn + u;
                float cold = g_c[idx];
                float c2 = fmaf(fv, cold, iv*gg);
                float h2 = ov * tanhf(c2);
                float hw, cw;
                if (!mode){
                    if (valid){ hw = h2; cw = c2; }
                    else      { hw = g_hF[pin][idx]; cw = cold; }
                    enc_out[((size_t)m*Tn + step)*Hn + u] = valid ? h2 : 0.0f;
                } else {
                    hw = h2; cw = c2;
                    g_dech[((size_t)step*Bn + m)*Hn + u] = h2;
                }
                g_c[idx] = cw;
                g_hF[pout][idx] = hw;
                bf16 hh = __float2bfloat16(hw);
                g_hH[pout][idx] = hh;
                g_hL[pout][idx] = __float2bfloat16(hw - __bfloat162float(hh));
            }
        }

        // ---- grid-wide barrier (proven form) ----
        __syncthreads();
        if (tid == 0){
            __threadfence();
            atomicAdd(&g_arrive, 1u);
            const unsigned goal = (unsigned)(it + 1) * gridDim.x;
            while (*((volatile unsigned*)&g_arrive) < goal) {}
            __threadfence();
        }
        __syncthreads();
    }
}

// ---------------------------------------------------------------------------
// Final output projection: out[b][s][:] = dech[s][b][:] @ lin_W^T + lin_b
// ---------------------------------------------------------------------------
__global__ __launch_bounds__(256, 1) void final_gemm_kernel(
    const float* __restrict__ linW, const float* __restrict__ linb,
    float* __restrict__ out){
    const int tid = threadIdx.x;
    const int tx = tid & 15, ty = tid >> 4;
    const int r0 = blockIdx.x << 6;
    const int n0 = blockIdx.y << 6;

    __shared__ __align__(16) float Asx[16][72];
    __shared__ __align__(16) float Wsx[16][72];
    float acc[4][4] = {};

    const int lrow = tid >> 2, lc4 = tid & 3;
    const float* aptr = g_dech + (size_t)(r0 + lrow)*Hn;
    const float* wptr = linW + (size_t)(n0 + lrow)*Hn;

    for (int k0 = 0; k0 < Hn; k0 += 16){
        const int k = k0 + lc4*4;
        float4 wv = *(const float4*)(wptr + k);
        float4 av = *(const float4*)(aptr + k);
        __syncthreads();
        Wsx[lc4*4 + 0][lrow] = wv.x; Wsx[lc4*4 + 1][lrow] = wv.y;
        Wsx[lc4*4 + 2][lrow] = wv.z; Wsx[lc4*4 + 3][lrow] = wv.w;
        Asx[lc4*4 + 0][lrow] = av.x; Asx[lc4*4 + 1][lrow] = av.y;
        Asx[lc4*4 + 2][lrow] = av.z; Asx[lc4*4 + 3][lrow] = av.w;
        __syncthreads();
        #pragma unroll
        for (int kk = 0; kk < 16; kk++){
            float4 a4 = *(const float4*)&Asx[kk][ty*4];
            float4 w4 = *(const float4*)&Wsx[kk][tx*4];
            float a[4] = {a4.x, a4.y, a4.z, a4.w};
            float w[4] = {w4.x, w4.y, w4.z, w4.w};
            #pragma unroll
            for (int i = 0; i < 4; i++)
                #pragma unroll
                for (int j = 0; j < 4; j++)
                    acc[i][j] = fmaf(a[i], w[j], acc[i][j]);
        }
    }

    #pragma unroll
    for (int r = 0; r < 4; r++){
        int rr = r0 + ty*4 + r;
        int s = rr >> 7;
        int b = rr & 127;
        int n = n0 + tx*4;
        float4 o;
        o.x = acc[r][0] + linb[n + 0];
        o.y = acc[r][1] + linb[n + 1];
        o.z = acc[r][2] + linb[n + 2];
        o.w = acc[r][3] + linb[n + 3];
        *(float4*)(out + ((size_t)b*Tn + s)*In + n) = o;
    }
}

// ---------------------------------------------------------------------------
// kernel_launch — 9 graph nodes. NO __device__ symbol is passed from host.
// Inputs: x_input, enc_Wih, enc_Whh, enc_bih, enc_bhh, dec_Wih, dec_Whh,
//         dec_bih, dec_bhh, lin_W, lin_b, lengths, tf_mask.
// Output: [outputs (B*T*I) | encoder_output (B*T*H)] float32.
// ---------------------------------------------------------------------------
extern "C" void kernel_launch(void* const* d_in, const int* in_sizes, int n_in,
                              void* d_out, int out_size){
    const float* x       = (const float*)d_in[0];
    const float* eWih    = (const float*)d_in[1];
    const float* eWhh    = (const float*)d_in[2];
    const float* ebih    = (const float*)d_in[3];
    const float* ebhh    = (const float*)d_in[4];
    const float* dWih    = (const float*)d_in[5];
    const float* dWhh    = (const float*)d_in[6];
    const float* dbih    = (const float*)d_in[7];
    const float* dbhh    = (const float*)d_in[8];
    const float* linW    = (const float*)d_in[9];
    const float* linb    = (const float*)d_in[10];
    const int*   lengths = (const int*)d_in[11];
    const int*   tfm     = (const int*)d_in[12];
    float* out = (float*)d_out;
    float* enc_out = out + (size_t)Bn*Tn*In;

    zero_state_kernel<<<(BHn + 255)/256, 256>>>();
    pack_wplanes_kernel<<<(int)(((size_t)Gn*KCAT + 255)/256), 256>>>(eWhh, eWih, 0, KCAT);
    pack_wplanes_kernel<<<(int)(((size_t)Gn*KCAT + 255)/256), 256>>>(dWhh, dWih, 1, KCAT);
    build_wsum_kernel<<<Gn, 256>>>(dWhh, dWih, linW);
    pack_wplanes_kernel<<<(int)(((size_t)Gn*KHn + 255)/256), 256>>>((const float*)0, (const float*)0, 2, KHn);
    build_bias_kernel<<<(Gn + 255)/256, 256>>>(ebih, ebhh, dbih, dbhh, dWih, linb);
    pack_x_kernel<<<(int)(((size_t)Tn*Bn*In + 255)/256), 256>>>(x);

    lstm_persist_kernel<<<128, 256>>>(lengths, tfm, enc_out);

    final_gemm_kernel<<<dim3((Tn*Bn)/64, In/64), 256>>>(linW, linb, out);
}

// round 8
// speedup vs baseline: 2.0362x; 1.1784x over previous
#include <cuda_runtime.h>
#include <cuda_bf16.h>
#include <math.h>
#include <stdint.h>
#include <mma.h>
using namespace nvcuda;

#define Bn 128
#define Tn 512
#define In 128
#define Hn 1024
#define Gn 4096
#define KHn 1024
#define KCAT 1152
#define BHn (Bn*Hn)

typedef __nv_bfloat16 bf16;

// Per-stage ring buffer: A planes 2*64*40 bf16 (5120) + W planes 5120 = 10240 bf16
#define STAGE_ELTS 10240
#define RING_DEPTH 3
#define SMEM_BYTES (RING_DEPTH * STAGE_ELTS * 2)   // 61440 B

// ---------------------------------------------------------------------------
// Static device scratch — ALL __device__ symbols referenced only in device code
// (host-passing a __device__ symbol silently uses the host shadow addr; on
// GB300/ATS the writes land in host memory without trapping — round-3/4/6 bug)
// ---------------------------------------------------------------------------
__device__ bf16 g_WencH[(size_t)Gn*KCAT], g_WencL[(size_t)Gn*KCAT];
__device__ bf16 g_WdecH[(size_t)Gn*KCAT], g_WdecL[(size_t)Gn*KCAT];
__device__ bf16 g_WsumH[(size_t)Gn*KHn],  g_WsumL[(size_t)Gn*KHn];
__device__ float g_wsum[(size_t)Gn*KHn];
__device__ bf16 g_xH[(size_t)Tn*Bn*In], g_xL[(size_t)Tn*Bn*In];  // [t][m][k]
__device__ bf16 g_hH[2][BHn], g_hL[2][BHn];                       // [m][h]
__device__ float g_hF[2][BHn];
__device__ float g_c[BHn];
__device__ float g_dech[(size_t)Tn*BHn];                          // [s][b][h]
__device__ float g_benc[Gn], g_bdec[Gn], g_b2dec[Gn];
__device__ unsigned g_arrive;

__device__ __forceinline__ float sigf(float x){ return 1.f/(1.f+__expf(-x)); }
__device__ __forceinline__ void cp16(uint32_t dst, const void* src){
    asm volatile("cp.async.cg.shared.global [%0],[%1],16;\n" :: "r"(dst), "l"(src));
}

// ---------------------------------------------------------------------------
// Prep kernels
// ---------------------------------------------------------------------------
__global__ void zero_state_kernel(){
    int i = blockIdx.x*blockDim.x + threadIdx.x;
    if (i == 0) g_arrive = 0u;
    if (i < BHn){
        g_hH[0][i] = __float2bfloat16(0.f);
        g_hL[0][i] = __float2bfloat16(0.f);
        g_hF[0][i] = 0.f;
        g_c[i] = 0.f;
    }
}

// which: 0 enc, 1 dec (src = harness Whh/Wih, K=KCAT); 2 sum (src g_wsum, K=KHn)
// dst[n][k]; packed col n -> unit n>>2, gate n&3 (src row = gate*H + unit)
__global__ void pack_wplanes_kernel(const float* __restrict__ Whh,
                                    const float* __restrict__ Wih,
                                    int which, int K){
    size_t idx = (size_t)blockIdx.x*256 + threadIdx.x;
    if (idx >= (size_t)Gn*K) return;
    int n = (int)(idx / K), k = (int)(idx - (size_t)n*K);
    int srcrow = (n & 3)*Hn + (n >> 2);
    float v;
    if (which == 2)
        v = g_wsum[(size_t)srcrow*KHn + k];
    else
        v = (k < KHn) ? Whh[(size_t)srcrow*KHn + k] : Wih[(size_t)srcrow*In + (k - KHn)];
    bf16* hiP = (which == 0) ? g_WencH : (which == 1) ? g_WdecH : g_WsumH;
    bf16* loP = (which == 0) ? g_WencL : (which == 1) ? g_WdecL : g_WsumL;
    bf16 hi = __float2bfloat16(v);
    hiP[idx] = hi;
    loP[idx] = __float2bfloat16(v - __bfloat162float(hi));
}

__global__ void pack_x_kernel(const float* __restrict__ x){
    size_t idx = (size_t)blockIdx.x*256 + threadIdx.x;
    if (idx >= (size_t)Tn*Bn*In) return;
    int k = (int)(idx & (In - 1));
    int m = (int)((idx >> 7) & (Bn - 1));
    int t = (int)(idx >> 14);
    float v = x[((size_t)m*Tn + t)*In + k];
    bf16 hi = __float2bfloat16(v);
    g_xH[idx] = hi;
    g_xL[idx] = __float2bfloat16(v - __bfloat162float(hi));
}

__global__ __launch_bounds__(256) void build_wsum_kernel(
    const float* __restrict__ Whh, const float* __restrict__ Wih,
    const float* __restrict__ linW){
    const int n = blockIdx.x;
    __shared__ float wr[In];
    if (threadIdx.x < In) wr[threadIdx.x] = Wih[n*In + threadIdx.x];
    __syncthreads();
    #pragma unroll
    for (int c = 0; c < 4; c++){
        int k = threadIdx.x + 256*c;
        float s = 0.0f;
        #pragma unroll 8
        for (int j = 0; j < In; j++) s = fmaf(wr[j], linW[j*Hn + k], s);
        g_wsum[(size_t)n*KHn + k] = Whh[(size_t)n*KHn + k] + s;
    }
}

__global__ void build_bias_kernel(const float* __restrict__ ebih, const float* __restrict__ ebhh,
                                  const float* __restrict__ dbih, const float* __restrict__ dbhh,
                                  const float* __restrict__ dWih, const float* __restrict__ linb){
    int n = blockIdx.x*blockDim.x + threadIdx.x;
    if (n < Gn){
        g_benc[n] = ebih[n] + ebhh[n];
        float bd = dbih[n] + dbhh[n];
        g_bdec[n] = bd;
        float s = 0.0f;
        #pragma unroll 8
        for (int j = 0; j < In; j++) s = fmaf(dWih[n*In + j], linb[j], s);
        g_b2dec[n] = bd + s;
    }
}

// ---------------------------------------------------------------------------
// Persistent recurrence: 3-term BF16 wmma, 3-deep cp.async.cg ring pipeline.
// 128 blocks x 256 threads; block tile 64(M) x 64(N); warp tile 16x32.
// Ring slot layout (bf16): A[pl2][64][40] at +0, W[pl2][64][40] at +5120.
// D f32[64][68] aliases ring slot 0 (only used after slot 0's last compute).
// ---------------------------------------------------------------------------
__global__ __launch_bounds__(256, 1) void lstm_persist_kernel(
    const int* __restrict__ lengths, const int* __restrict__ tf_mask,
    float* __restrict__ enc_out){
    extern __shared__ __align__(16) bf16 RING[];
    float* Dsm = (float*)RING;                       // [64][68] alias
    const uint32_t ring_base = (uint32_t)__cvta_generic_to_shared(RING);
    const int tid = threadIdx.x, wid = tid >> 5;
    const int wm = wid & 3, wn = wid >> 2;
    const int mt = blockIdx.x >> 6, nt = blockIdx.x & 63;

    for (int it = 0; it < 2*Tn; it++){
        const int mode = it >= Tn;
        const int step = mode ? it - Tn : it;
        const int pin = it & 1, pout = pin ^ 1;

        const bf16 *WH, *WL; const float* bias; int K, ts;
        if (!mode){ WH = g_WencH; WL = g_WencL; bias = g_benc; K = KCAT; ts = step; }
        else {
            int teach;
            if (step == 0){ teach = 1; ts = Tn - 1; }
            else          { teach = tf_mask[step - 1]; ts = step - 1; }
            if (teach){ WH = g_WdecH; WL = g_WdecL; bias = g_bdec;  K = KCAT; }
            else      { WH = g_WsumH; WL = g_WsumL; bias = g_b2dec; K = KHn;  }
        }
        const int nst = K >> 5;
        const bf16* hHp = g_hH[pin];
        const bf16* hLp = g_hL[pin];

        wmma::fragment<wmma::accumulator,16,16,16,float> acc[2];
        wmma::fill_fragment(acc[0], 0.0f);
        wmma::fill_fragment(acc[1], 0.0f);

        // issue one BK=32 stage into ring slot s%3 (4x cp.async 16B per thread)
        auto issue = [&](int s){
            const int k0 = s << 5;
            const uint32_t sb = ring_base + (uint32_t)(s % RING_DEPTH) * (STAGE_ELTS*2);
            #pragma unroll
            for (int i = 0; i < 4; i++){
                int c = tid + (i << 8);                 // 0..1023
                if (c < 512){                           // A chunks
                    int row = c >> 3, pl = (c >> 2) & 1, q = c & 3;
                    int k = k0 + (q << 3);
                    const bf16* p;
                    if (k < KHn) p = (pl ? hLp : hHp) + (size_t)(mt*64 + row)*KHn + k;
                    else         p = (pl ? g_xL : g_xH) + ((size_t)ts*Bn + mt*64 + row)*In + (k - KHn);
                    cp16(sb + (uint32_t)(((pl*64 + row)*40 + (q << 3)) * 2), p);
                } else {                                // W chunks
                    int c2 = c - 512;
                    int row = c2 >> 3, pl = (c2 >> 2) & 1, q = c2 & 3;
                    int k = k0 + (q << 3);
                    const bf16* p = (pl ? WL : WH) + (size_t)(nt*64 + row)*K + k;
                    cp16(sb + (uint32_t)((5120 + (pl*64 + row)*40 + (q << 3)) * 2), p);
                }
            }
            asm volatile("cp.async.commit_group;\n");
        };

        issue(0); issue(1); issue(2);

        for (int s = 0; s < nst; s++){
            if (s < nst - 2)      asm volatile("cp.async.wait_group 2;\n");
            else if (s == nst - 2) asm volatile("cp.async.wait_group 1;\n");
            else                   asm volatile("cp.async.wait_group 0;\n");
            __syncthreads();                      // stage s data visible to all
            const bf16* SB = RING + (size_t)(s % RING_DEPTH) * STAGE_ELTS;
            #pragma unroll
            for (int kcl = 0; kcl < 2; kcl++){
                wmma::fragment<wmma::matrix_a,16,16,16,bf16,wmma::row_major> aH, aL;
                wmma::fragment<wmma::matrix_b,16,16,16,bf16,wmma::col_major> bH[2], bL[2];
                wmma::load_matrix_sync(aH, SB + (0*64 + wm*16)*40 + kcl*16, 40);
                wmma::load_matrix_sync(aL, SB + (1*64 + wm*16)*40 + kcl*16, 40);
                #pragma unroll
                for (int nf = 0; nf < 2; nf++){
                    wmma::load_matrix_sync(bH[nf], SB + 5120 + (0*64 + wn*32 + nf*16)*40 + kcl*16, 40);
                    wmma::load_matrix_sync(bL[nf], SB + 5120 + (1*64 + wn*32 + nf*16)*40 + kcl*16, 40);
                }
                #pragma unroll
                for (int nf = 0; nf < 2; nf++){
                    wmma::mma_sync(acc[nf], aH, bH[nf], acc[nf]);   // hh
                    wmma::mma_sync(acc[nf], aH, bL[nf], acc[nf]);   // hl
                    wmma::mma_sync(acc[nf], aL, bH[nf], acc[nf]);   // lh  (ll dropped)
                }
            }
            __syncthreads();                      // all reads of slot s done
            if (s + RING_DEPTH < nst) issue(s + RING_DEPTH);  // refill freed slot
        }

        // ---- D -> smem (aliases slot 0; safe: all computes finished) ----
        wmma::store_matrix_sync(&Dsm[(wm*16)*68 + wn*32 +  0], acc[0], 68, wmma::mem_row_major);
        wmma::store_matrix_sync(&Dsm[(wm*16)*68 + wn*32 + 16], acc[1], 68, wmma::mem_row_major);
        __syncthreads();

        // ---- layout-free epilogue: each thread = 1 batch row x 4 units ----
        {
            const int ml = tid >> 2;
            const int m  = mt*64 + ml;
            const bool valid = mode ? true : (step < lengths[m]);
            #pragma unroll
            for (int j = 0; j < 4; j++){
                const int ul = (tid & 3)*4 + j;
                const int u  = nt*16 + ul;
                float4 gv = *(const float4*)&Dsm[ml*68 + ul*4];   // i,f,g,o
                float iv = sigf(gv.x + bias[u]);
                float fv = sigf(gv.y + bias[Hn + u]);
                float gg = tanhf(gv.z + bias[2*Hn + u]);
                float ov = sigf(gv.w + bias[3*Hn + u]);
                const size_t idx = (size_t)m*Hn + u;
                float cold = g_c[idx];
                float c2 = fmaf(fv, cold, iv*gg);
                float h2 = ov * tanhf(c2);
                float hw, cw;
                if (!mode){
                    if (valid){ hw = h2; cw = c2; }
                    else      { hw = g_hF[pin][idx]; cw = cold; }
                    enc_out[((size_t)m*Tn + step)*Hn + u] = valid ? h2 : 0.0f;
                } else {
                    hw = h2; cw = c2;
                    g_dech[((size_t)step*Bn + m)*Hn + u] = h2;
                }
                g_c[idx] = cw;
                g_hF[pout][idx] = hw;
                bf16 hh = __float2bfloat16(hw);
                g_hH[pout][idx] = hh;
                g_hL[pout][idx] = __float2bfloat16(hw - __bfloat162float(hh));
            }
        }

        // ---- grid-wide barrier (proven form) ----
        __syncthreads();
        if (tid == 0){
            __threadfence();
            atomicAdd(&g_arrive, 1u);
            const unsigned goal = (unsigned)(it + 1) * gridDim.x;
            while (*((volatile unsigned*)&g_arrive) < goal) {}
            __threadfence();
        }
        __syncthreads();
    }
}

// ---------------------------------------------------------------------------
// Final output projection: out[b][s][:] = dech[s][b][:] @ lin_W^T + lin_b
// ---------------------------------------------------------------------------
__global__ __launch_bounds__(256, 1) void final_gemm_kernel(
    const float* __restrict__ linW, const float* __restrict__ linb,
    float* __restrict__ out){
    const int tid = threadIdx.x;
    const int tx = tid & 15, ty = tid >> 4;
    const int r0 = blockIdx.x << 6;
    const int n0 = blockIdx.y << 6;

    __shared__ __align__(16) float Asx[16][72];
    __shared__ __align__(16) float Wsx[16][72];
    float acc[4][4] = {};

    const int lrow = tid >> 2, lc4 = tid & 3;
    const float* aptr = g_dech + (size_t)(r0 + lrow)*Hn;
    const float* wptr = linW + (size_t)(n0 + lrow)*Hn;

    for (int k0 = 0; k0 < Hn; k0 += 16){
        const int k = k0 + lc4*4;
        float4 wv = *(const float4*)(wptr + k);
        float4 av = *(const float4*)(aptr + k);
        __syncthreads();
        Wsx[lc4*4 + 0][lrow] = wv.x; Wsx[lc4*4 + 1][lrow] = wv.y;
        Wsx[lc4*4 + 2][lrow] = wv.z; Wsx[lc4*4 + 3][lrow] = wv.w;
        Asx[lc4*4 + 0][lrow] = av.x; Asx[lc4*4 + 1][lrow] = av.y;
        Asx[lc4*4 + 2][lrow] = av.z; Asx[lc4*4 + 3][lrow] = av.w;
        __syncthreads();
        #pragma unroll
        for (int kk = 0; kk < 16; kk++){
            float4 a4 = *(const float4*)&Asx[kk][ty*4];
            float4 w4 = *(const float4*)&Wsx[kk][tx*4];
            float a[4] = {a4.x, a4.y, a4.z, a4.w};
            float w[4] = {w4.x, w4.y, w4.z, w4.w};
            #pragma unroll
            for (int i = 0; i < 4; i++)
                #pragma unroll
                for (int j = 0; j < 4; j++)
                    acc[i][j] = fmaf(a[i], w[j], acc[i][j]);
        }
    }

    #pragma unroll
    for (int r = 0; r < 4; r++){
        int rr = r0 + ty*4 + r;
        int s = rr >> 7;
        int b = rr & 127;
        int n = n0 + tx*4;
        float4 o;
        o.x = acc[r][0] + linb[n + 0];
        o.y = acc[r][1] + linb[n + 1];
        o.z = acc[r][2] + linb[n + 2];
        o.w = acc[r][3] + linb[n + 3];
        *(float4*)(out + ((size_t)b*Tn + s)*In + n) = o;
    }
}

// ---------------------------------------------------------------------------
// kernel_launch — 9 graph nodes. No __device__ symbol passed from host.
// Inputs: x_input, enc_Wih, enc_Whh, enc_bih, enc_bhh, dec_Wih, dec_Whh,
//         dec_bih, dec_bhh, lin_W, lin_b, lengths, tf_mask.
// Output: [outputs (B*T*I) | encoder_output (B*T*H)] float32.
// ---------------------------------------------------------------------------
extern "C" void kernel_launch(void* const* d_in, const int* in_sizes, int n_in,
                              void* d_out, int out_size){
    const float* x       = (const float*)d_in[0];
    const float* eWih    = (const float*)d_in[1];
    const float* eWhh    = (const float*)d_in[2];
    const float* ebih    = (const float*)d_in[3];
    const float* ebhh    = (const float*)d_in[4];
    const float* dWih    = (const float*)d_in[5];
    const float* dWhh    = (const float*)d_in[6];
    const float* dbih    = (const float*)d_in[7];
    const float* dbhh    = (const float*)d_in[8];
    const float* linW    = (const float*)d_in[9];
    const float* linb    = (const float*)d_in[10];
    const int*   lengths = (const int*)d_in[11];
    const int*   tfm     = (const int*)d_in[12];
    float* out = (float*)d_out;
    float* enc_out = out + (size_t)Bn*Tn*In;

    cudaFuncSetAttribute(lstm_persist_kernel,
                         cudaFuncAttributeMaxDynamicSharedMemorySize, SMEM_BYTES);

    zero_state_kernel<<<(BHn + 255)/256, 256>>>();
    pack_wplanes_kernel<<<(int)(((size_t)Gn*KCAT + 255)/256), 256>>>(eWhh, eWih, 0, KCAT);
    pack_wplanes_kernel<<<(int)(((size_t)Gn*KCAT + 255)/256), 256>>>(dWhh, dWih, 1, KCAT);
    build_wsum_kernel<<<Gn, 256>>>(dWhh, dWih, linW);
    pack_wplanes_kernel<<<(int)(((size_t)Gn*KHn + 255)/256), 256>>>((const float*)0, (const float*)0, 2, KHn);
    build_bias_kernel<<<(Gn + 255)/256, 256>>>(ebih, ebhh, dbih, dbhh, dWih, linb);
    pack_x_kernel<<<(int)(((size_t)Tn*Bn*In + 255)/256), 256>>>(x);

    lstm_persist_kernel<<<128, 256, SMEM_BYTES>>>(lengths, tfm, enc_out);

    final_gemm_kernel<<<dim3((Tn*Bn)/64, In/64), 256>>>(linW, linb, out);
}

// round 11
// speedup vs baseline: 3.2046x; 1.5738x over previous
#include <cuda_runtime.h>
#include <cuda_fp16.h>
#include <math.h>
#include <stdint.h>
#include <mma.h>
using namespace nvcuda;

#define Bn 128
#define Tn 512
#define In 128
#define Hn 1024
#define Gn 4096
#define KHn 1024
#define KCAT 1152
#define BHn (Bn*Hn)

// Stage: AH[64][72] + AL[64][72] + BH[64][72] half = 27648 B; ring of 4.
#define PITCH 72
#define OFF_AHh 0
#define OFF_ALh 4608            // 64*72 halves
#define OFF_BHh 9216
#define STAGE_BYTES 27648
#define RING_DEPTH 4
#define SMEM_BYTES (RING_DEPTH*STAGE_BYTES)   // 110592 B

// ---------------------------------------------------------------------------
// Static device scratch — referenced ONLY from device code (GB300/ATS trap:
// host-passing a __device__ symbol silently uses the host shadow address)
// ---------------------------------------------------------------------------
__device__ __half g_Wenc[(size_t)Gn*KCAT];     // fp16 single plane, [n][k]
__device__ __half g_Wdec[(size_t)Gn*KCAT];
__device__ __half g_Wsum16[(size_t)Gn*KHn];
__device__ float  g_wsum[(size_t)Gn*KHn];
__device__ __half g_xH[(size_t)Tn*Bn*In], g_xL[(size_t)Tn*Bn*In];  // [t][m][k]
__device__ __half g_hH[2][BHn], g_hL[2][BHn];                      // [m][h]
__device__ float  g_hF[2][BHn];
__device__ float  g_c[BHn];
__device__ float  g_dech[(size_t)Tn*BHn];                          // [s][b][h]
__device__ float  g_benc[Gn], g_bdec[Gn], g_b2dec[Gn];
__device__ unsigned g_arrive;

__device__ __forceinline__ float sigf(float x){ return 1.f/(1.f+__expf(-x)); }
__device__ __forceinline__ void cp16(uint32_t dst, const void* src){
    asm volatile("cp.async.cg.shared.global [%0],[%1],16;\n" :: "r"(dst), "l"(src));
}

// ---------------------------------------------------------------------------
// Prep kernels (elementwise)
// ---------------------------------------------------------------------------
__global__ void zero_state_kernel(){
    int i = blockIdx.x*blockDim.x + threadIdx.x;
    if (i == 0) g_arrive = 0u;
    if (i < BHn){
        g_hH[0][i] = __float2half(0.f);
        g_hL[0][i] = __float2half(0.f);
        g_hF[0][i] = 0.f;
        g_c[i] = 0.f;
    }
}

// which: 0 enc, 1 dec (src harness Whh/Wih, K=KCAT); 2 sum (src g_wsum, K=KHn)
// dst[n][k]; packed col n -> unit n>>2, gate n&3 (src row = gate*H + unit)
__global__ void pack_w_kernel(const float* __restrict__ Whh,
                              const float* __restrict__ Wih,
                              int which, int K){
    size_t idx = (size_t)blockIdx.x*256 + threadIdx.x;
    if (idx >= (size_t)Gn*K) return;
    int n = (int)(idx / K), k = (int)(idx - (size_t)n*K);
    int srcrow = (n & 3)*Hn + (n >> 2);
    float v;
    if (which == 2)
        v = g_wsum[(size_t)srcrow*KHn + k];
    else
        v = (k < KHn) ? Whh[(size_t)srcrow*KHn + k] : Wih[(size_t)srcrow*In + (k - KHn)];
    __half* P = (which == 0) ? g_Wenc : (which == 1) ? g_Wdec : g_Wsum16;
    P[idx] = __float2half(v);
}

__global__ void pack_x_kernel(const float* __restrict__ x){
    size_t idx = (size_t)blockIdx.x*256 + threadIdx.x;
    if (idx >= (size_t)Tn*Bn*In) return;
    int k = (int)(idx & (In - 1));
    int m = (int)((idx >> 7) & (Bn - 1));
    int t = (int)(idx >> 14);
    float v = x[((size_t)m*Tn + t)*In + k];
    __half hi = __float2half(v);
    g_xH[idx] = hi;
    g_xL[idx] = __float2half(v - __half2float(hi));
}

__global__ __launch_bounds__(256) void build_wsum_kernel(
    const float* __restrict__ Whh, const float* __restrict__ Wih,
    const float* __restrict__ linW){
    const int n = blockIdx.x;
    __shared__ float wr[In];
    if (threadIdx.x < In) wr[threadIdx.x] = Wih[n*In + threadIdx.x];
    __syncthreads();
    #pragma unroll
    for (int c = 0; c < 4; c++){
        int k = threadIdx.x + 256*c;
        float s = 0.0f;
        #pragma unroll 8
        for (int j = 0; j < In; j++) s = fmaf(wr[j], linW[j*Hn + k], s);
        g_wsum[(size_t)n*KHn + k] = Whh[(size_t)n*KHn + k] + s;
    }
}

__global__ void build_bias_kernel(const float* __restrict__ ebih, const float* __restrict__ ebhh,
                                  const float* __restrict__ dbih, const float* __restrict__ dbhh,
                                  const float* __restrict__ dWih, const float* __restrict__ linb){
    int n = blockIdx.x*blockDim.x + threadIdx.x;
    if (n < Gn){
        g_benc[n] = ebih[n] + ebhh[n];
        float bd = dbih[n] + dbhh[n];
        g_bdec[n] = bd;
        float s = 0.0f;
        #pragma unroll 8
        for (int j = 0; j < In; j++) s = fmaf(dWih[n*In + j], linb[j], s);
        g_b2dec[n] = bd + s;
    }
}

// ---------------------------------------------------------------------------
// Persistent recurrence: 2-term FP16 wmma (A hi/lo split, W single plane).
// 128 CTAs x 256 threads; block tile 64(M) x 64(N); warp tile 16x32.
// BK=64 stages, 4-deep cp.async.cg ring, prefetch distance 3.
// D f32[64][68] aliases ring slot 0 (used only after all compute).
// ---------------------------------------------------------------------------
__global__ __launch_bounds__(256, 1) void lstm_persist_kernel(
    const int* __restrict__ lengths, const int* __restrict__ tf_mask,
    float* __restrict__ enc_out){
    extern __shared__ __align__(16) char DS[];
    __half* RINGh = (__half*)DS;
    float*  Dsm   = (float*)DS;                 // [64][68] alias of slot 0
    const uint32_t ring_base = (uint32_t)__cvta_generic_to_shared(DS);
    const int tid = threadIdx.x, wid = tid >> 5;
    const int wm = wid & 3, wn = wid >> 2;      // warp rows wm*16, cols wn*32
    const int mt = blockIdx.x >> 6, nt = blockIdx.x & 63;

    for (int it = 0; it < 2*Tn; it++){
        const int mode = it >= Tn;
        const int step = mode ? it - Tn : it;
        const int pin = it & 1, pout = pin ^ 1;

        const __half* W; const float* bias; int K, ts;
        if (!mode){ W = g_Wenc; bias = g_benc; K = KCAT; ts = step; }
        else {
            int teach;
            if (step == 0){ teach = 1; ts = Tn - 1; }
            else          { teach = tf_mask[step - 1]; ts = step - 1; }
            if (teach){ W = g_Wdec;   bias = g_bdec;  K = KCAT; }
            else      { W = g_Wsum16; bias = g_b2dec; K = KHn;  }
        }
        const int nst = K >> 6;                 // BK=64 stages (18 or 16)
        const __half* hHp = g_hH[pin];
        const __half* hLp = g_hL[pin];

        wmma::fragment<wmma::accumulator,16,16,16,float> acc[2];
        wmma::fill_fragment(acc[0], 0.0f);
        wmma::fill_fragment(acc[1], 0.0f);

        // issue one BK=64 stage into ring slot s&3: 6x cp.async 16B per thread
        auto issue = [&](int s){
            const int k0 = s << 6;
            const uint32_t sb = ring_base + (uint32_t)(s & 3)*STAGE_BYTES;
            #pragma unroll
            for (int i = 0; i < 6; i++){
                int c16 = tid + (i << 8);              // 0..1535
                if (c16 < 1024){                       // A: 2 planes x 64r x 8 chunks
                    int pl = c16 >> 9, r = (c16 >> 3) & 63, q = c16 & 7;
                    int k = k0 + (q << 3);
                    const __half* p;
                    if (k < KHn) p = (pl ? hLp : hHp) + (size_t)(mt*64 + r)*KHn + k;
                    else         p = (pl ? g_xL : g_xH) + ((size_t)ts*Bn + mt*64 + r)*In + (k - KHn);
                    cp16(sb + (uint32_t)(((pl ? OFF_ALh : OFF_AHh) + r*PITCH + (q << 3)) * 2), p);
                } else {                               // B: 64r x 8 chunks
                    int c2 = c16 - 1024;
                    int r = (c2 >> 3) & 63, q = c2 & 7;
                    const __half* p = W + (size_t)(nt*64 + r)*K + k0 + (q << 3);
                    cp16(sb + (uint32_t)((OFF_BHh + r*PITCH + (q << 3)) * 2), p);
                }
            }
            asm volatile("cp.async.commit_group;\n");
        };

        issue(0); issue(1); issue(2);

        for (int s = 0; s < nst; s++){
            if (s + 3 < nst) issue(s + 3);      // slot (s-1)&3 freed by last sync
            const int rem = nst - 1 - s;        // groups issued after stage s
            if (rem >= 3)      asm volatile("cp.async.wait_group 3;\n");
            else if (rem == 2) asm volatile("cp.async.wait_group 2;\n");
            else if (rem == 1) asm volatile("cp.async.wait_group 1;\n");
            else               asm volatile("cp.async.wait_group 0;\n");
            __syncthreads();                    // stage s visible to all
            const __half* SB = RINGh + (size_t)(s & 3)*(STAGE_BYTES/2);
            #pragma unroll
            for (int kcl = 0; kcl < 4; kcl++){
                wmma::fragment<wmma::matrix_a,16,16,16,__half,wmma::row_major> aH, aL;
                wmma::fragment<wmma::matrix_b,16,16,16,__half,wmma::col_major> b0, b1;
                wmma::load_matrix_sync(aH, SB + OFF_AHh + (wm*16)*PITCH + kcl*16, PITCH);
                wmma::load_matrix_sync(aL, SB + OFF_ALh + (wm*16)*PITCH + kcl*16, PITCH);
                wmma::load_matrix_sync(b0, SB + OFF_BHh + (wn*32)*PITCH + kcl*16, PITCH);
                wmma::load_matrix_sync(b1, SB + OFF_BHh + (wn*32 + 16)*PITCH + kcl*16, PITCH);
                wmma::mma_sync(acc[0], aH, b0, acc[0]);
                wmma::mma_sync(acc[0], aL, b0, acc[0]);
                wmma::mma_sync(acc[1], aH, b1, acc[1]);
                wmma::mma_sync(acc[1], aL, b1, acc[1]);
            }
            __syncthreads();                    // all reads of slot s done
        }

        // ---- D -> smem (aliases slot 0; all compute finished) ----
        wmma::store_matrix_sync(&Dsm[(wm*16)*68 + wn*32 +  0], acc[0], 68, wmma::mem_row_major);
        wmma::store_matrix_sync(&Dsm[(wm*16)*68 + wn*32 + 16], acc[1], 68, wmma::mem_row_major);
        __syncthreads();

        // ---- layout-free epilogue: each thread = 1 batch row x 4 units ----
        {
            const int ml = tid >> 2;
            const int m  = mt*64 + ml;
            const bool valid = mode ? true : (step < lengths[m]);
            #pragma unroll
            for (int j = 0; j < 4; j++){
                const int ul = (tid & 3)*4 + j;
                const int u  = nt*16 + ul;
                float4 gv = *(const float4*)&Dsm[ml*68 + ul*4];   // i,f,g,o
                float iv = sigf(gv.x + bias[u]);
                float fv = sigf(gv.y + bias[Hn + u]);
                float gg = tanhf(gv.z + bias[2*Hn + u]);
                float ov = sigf(gv.w + bias[3*Hn + u]);
                const size_t idx = (size_t)m*Hn + u;
                float cold = g_c[idx];
                float c2 = fmaf(fv, cold, iv*gg);
                float h2 = ov * tanhf(c2);
                float hw, cw;
                if (!mode){
                    if (valid){ hw = h2; cw = c2; }
                    else      { hw = g_hF[pin][idx]; cw = cold; }
                    enc_out[((size_t)m*Tn + step)*Hn + u] = valid ? h2 : 0.0f;
                } else {
                    hw = h2; cw = c2;
                    g_dech[((size_t)step*Bn + m)*Hn + u] = h2;
                }
                g_c[idx] = cw;
                g_hF[pout][idx] = hw;
                __half hh = __float2half(hw);
                g_hH[pout][idx] = hh;
                g_hL[pout][idx] = __float2half(hw - __half2float(hh));
            }
        }

        // ---- grid-wide barrier (proven form) ----
        __syncthreads();
        if (tid == 0){
            __threadfence();
            atomicAdd(&g_arrive, 1u);
            const unsigned goal = (unsigned)(it + 1) * gridDim.x;
            while (*((volatile unsigned*)&g_arrive) < goal) {}
            __threadfence();
        }
        __syncthreads();
    }
}

// ---------------------------------------------------------------------------
// Final output projection: out[b][s][:] = dech[s][b][:] @ lin_W^T + lin_b
// ---------------------------------------------------------------------------
__global__ __launch_bounds__(256, 1) void final_gemm_kernel(
    const float* __restrict__ linW, const float* __restrict__ linb,
    float* __restrict__ out){
    const int tid = threadIdx.x;
    const int tx = tid & 15, ty = tid >> 4;
    const int r0 = blockIdx.x << 6;
    const int n0 = blockIdx.y << 6;

    __shared__ __align__(16) float Asx[16][72];
    __shared__ __align__(16) float Wsx[16][72];
    float acc[4][4] = {};

    const int lrow = tid >> 2, lc4 = tid & 3;
    const float* aptr = g_dech + (size_t)(r0 + lrow)*Hn;
    const float* wptr = linW + (size_t)(n0 + lrow)*Hn;

    for (int k0 = 0; k0 < Hn; k0 += 16){
        const int k = k0 + lc4*4;
        float4 wv = *(const float4*)(wptr + k);
        float4 av = *(const float4*)(aptr + k);
        __syncthreads();
        Wsx[lc4*4 + 0][lrow] = wv.x; Wsx[lc4*4 + 1][lrow] = wv.y;
        Wsx[lc4*4 + 2][lrow] = wv.z; Wsx[lc4*4 + 3][lrow] = wv.w;
        Asx[lc4*4 + 0][lrow] = av.x; Asx[lc4*4 + 1][lrow] = av.y;
        Asx[lc4*4 + 2][lrow] = av.z; Asx[lc4*4 + 3][lrow] = av.w;
        __syncthreads();
        #pragma unroll
        for (int kk = 0; kk < 16; kk++){
            float4 a4 = *(const float4*)&Asx[kk][ty*4];
            float4 w4 = *(const float4*)&Wsx[kk][tx*4];
            float a[4] = {a4.x, a4.y, a4.z, a4.w};
            float w[4] = {w4.x, w4.y, w4.z, w4.w};
            #pragma unroll
            for (int i = 0; i < 4; i++)
                #pragma unroll
                for (int j = 0; j < 4; j++)
                    acc[i][j] = fmaf(a[i], w[j], acc[i][j]);
        }
    }

    #pragma unroll
    for (int r = 0; r < 4; r++){
        int rr = r0 + ty*4 + r;
        int s = rr >> 7;
        int b = rr & 127;
        int n = n0 + tx*4;
        float4 o;
        o.x = acc[r][0] + linb[n + 0];
        o.y = acc[r][1] + linb[n + 1];
        o.z = acc[r][2] + linb[n + 2];
        o.w = acc[r][3] + linb[n + 3];
        *(float4*)(out + ((size_t)b*Tn + s)*In + n) = o;
    }
}

// ---------------------------------------------------------------------------
// kernel_launch — 9 graph nodes. No __device__ symbol passed from host.
// Inputs: x_input, enc_Wih, enc_Whh, enc_bih, enc_bhh, dec_Wih, dec_Whh,
//         dec_bih, dec_bhh, lin_W, lin_b, lengths, tf_mask.
// Output: [outputs (B*T*I) | encoder_output (B*T*H)] float32.
// ---------------------------------------------------------------------------
extern "C" void kernel_launch(void* const* d_in, const int* in_sizes, int n_in,
                              void* d_out, int out_size){
    const float* x       = (const float*)d_in[0];
    const float* eWih    = (const float*)d_in[1];
    const float* eWhh    = (const float*)d_in[2];
    const float* ebih    = (const float*)d_in[3];
    const float* ebhh    = (const float*)d_in[4];
    const float* dWih    = (const float*)d_in[5];
    const float* dWhh    = (const float*)d_in[6];
    const float* dbih    = (const float*)d_in[7];
    const float* dbhh    = (const float*)d_in[8];
    const float* linW    = (const float*)d_in[9];
    const float* linb    = (const float*)d_in[10];
    const int*   lengths = (const int*)d_in[11];
    const int*   tfm     = (const int*)d_in[12];
    float* out = (float*)d_out;
    float* enc_out = out + (size_t)Bn*Tn*In;

    cudaFuncSetAttribute(lstm_persist_kernel,
                         cudaFuncAttributeMaxDynamicSharedMemorySize, SMEM_BYTES);

    zero_state_kernel<<<(BHn + 255)/256, 256>>>();
    pack_w_kernel<<<(int)(((size_t)Gn*KCAT + 255)/256), 256>>>(eWhh, eWih, 0, KCAT);
    pack_w_kernel<<<(int)(((size_t)Gn*KCAT + 255)/256), 256>>>(dWhh, dWih, 1, KCAT);
    build_wsum_kernel<<<Gn, 256>>>(dWhh, dWih, linW);
    pack_w_kernel<<<(int)(((size_t)Gn*KHn + 255)/256), 256>>>((const float*)0, (const float*)0, 2, KHn);
    build_bias_kernel<<<(Gn + 255)/256, 256>>>(ebih, ebhh, dbih, dbhh, dWih, linb);
    pack_x_kernel<<<(int)(((size_t)Tn*Bn*In + 255)/256), 256>>>(x);

    lstm_persist_kernel<<<128, 256, SMEM_BYTES>>>(lengths, tfm, enc_out);

    final_gemm_kernel<<<dim3((Tn*Bn)/64, In/64), 256>>>(linW, linb, out);
}

// round 12
// speedup vs baseline: 3.3506x; 1.0456x over previous
#include <cuda_runtime.h>
#include <cuda_fp16.h>
#include <math.h>
#include <stdint.h>
#include <mma.h>
using namespace nvcuda;

#define Bn 128
#define Tn 512
#define In 128
#define Hn 1024
#define Gn 4096
#define KHn 1024
#define KCAT 1152
#define BHn (Bn*Hn)

// Stage: AH[64][72] + AL[64][72] + BH[64][72] half = 27648 B; ring of 4.
#define PITCH 72
#define OFF_AHh 0
#define OFF_ALh 4608            // 64*72 halves
#define OFF_BHh 9216
#define STAGE_BYTES 27648
#define SMEM_BYTES (4*STAGE_BYTES)   // 110592 B

// ---------------------------------------------------------------------------
// Static device scratch — referenced ONLY from device code (GB300/ATS trap:
// host-passing a __device__ symbol silently uses the host shadow address)
// ---------------------------------------------------------------------------
__device__ __half g_Wenc[(size_t)Gn*KCAT];     // fp16 single plane, [n][k]
__device__ __half g_Wdec[(size_t)Gn*KCAT];
__device__ __half g_Wsum16[(size_t)Gn*KHn];
__device__ float  g_wsum[(size_t)Gn*KHn];
__device__ __half g_xH[(size_t)Tn*Bn*In], g_xL[(size_t)Tn*Bn*In];  // [t][m][k]
__device__ __half g_hH[2][BHn], g_hL[2][BHn];                      // [m][h]
__device__ float  g_hF[2][BHn];
__device__ float  g_c[BHn];
__device__ float  g_dech[(size_t)Tn*BHn];                          // [s][b][h]
__device__ float  g_benc[Gn], g_bdec[Gn], g_b2dec[Gn];
__device__ unsigned g_arrive;

__device__ __forceinline__ float sigf(float x){ return 1.f/(1.f+__expf(-x)); }
__device__ __forceinline__ void cp16(uint32_t dst, const void* src){
    asm volatile("cp.async.cg.shared.global [%0],[%1],16;\n" :: "r"(dst), "l"(src));
}

// ---------------------------------------------------------------------------
// Prep kernels (elementwise)
// ---------------------------------------------------------------------------
__global__ void zero_state_kernel(){
    int i = blockIdx.x*blockDim.x + threadIdx.x;
    if (i == 0) g_arrive = 0u;
    if (i < BHn){
        g_hH[0][i] = __float2half(0.f);
        g_hL[0][i] = __float2half(0.f);
        g_hF[0][i] = 0.f;
        g_c[i] = 0.f;
    }
}

// which: 0 enc, 1 dec (src harness Whh/Wih, K=KCAT); 2 sum (src g_wsum, K=KHn)
// dst[n][k]; packed col n -> unit n>>2, gate n&3 (src row = gate*H + unit)
__global__ void pack_w_kernel(const float* __restrict__ Whh,
                              const float* __restrict__ Wih,
                              int which, int K){
    size_t idx = (size_t)blockIdx.x*256 + threadIdx.x;
    if (idx >= (size_t)Gn*K) return;
    int n = (int)(idx / K), k = (int)(idx - (size_t)n*K);
    int srcrow = (n & 3)*Hn + (n >> 2);
    float v;
    if (which == 2)
        v = g_wsum[(size_t)srcrow*KHn + k];
    else
        v = (k < KHn) ? Whh[(size_t)srcrow*KHn + k] : Wih[(size_t)srcrow*In + (k - KHn)];
    __half* P = (which == 0) ? g_Wenc : (which == 1) ? g_Wdec : g_Wsum16;
    P[idx] = __float2half(v);
}

__global__ void pack_x_kernel(const float* __restrict__ x){
    size_t idx = (size_t)blockIdx.x*256 + threadIdx.x;
    if (idx >= (size_t)Tn*Bn*In) return;
    int k = (int)(idx & (In - 1));
    int m = (int)((idx >> 7) & (Bn - 1));
    int t = (int)(idx >> 14);
    float v = x[((size_t)m*Tn + t)*In + k];
    __half hi = __float2half(v);
    g_xH[idx] = hi;
    g_xL[idx] = __float2half(v - __half2float(hi));
}

__global__ __launch_bounds__(256) void build_wsum_kernel(
    const float* __restrict__ Whh, const float* __restrict__ Wih,
    const float* __restrict__ linW){
    const int n = blockIdx.x;
    __shared__ float wr[In];
    if (threadIdx.x < In) wr[threadIdx.x] = Wih[n*In + threadIdx.x];
    __syncthreads();
    #pragma unroll
    for (int c = 0; c < 4; c++){
        int k = threadIdx.x + 256*c;
        float s = 0.0f;
        #pragma unroll 8
        for (int j = 0; j < In; j++) s = fmaf(wr[j], linW[j*Hn + k], s);
        g_wsum[(size_t)n*KHn + k] = Whh[(size_t)n*KHn + k] + s;
    }
}

__global__ void build_bias_kernel(const float* __restrict__ ebih, const float* __restrict__ ebhh,
                                  const float* __restrict__ dbih, const float* __restrict__ dbhh,
                                  const float* __restrict__ dWih, const float* __restrict__ linb){
    int n = blockIdx.x*blockDim.x + threadIdx.x;
    if (n < Gn){
        g_benc[n] = ebih[n] + ebhh[n];
        float bd = dbih[n] + dbhh[n];
        g_bdec[n] = bd;
        float s = 0.0f;
        #pragma unroll 8
        for (int j = 0; j < In; j++) s = fmaf(dWih[n*In + j], linb[j], s);
        g_b2dec[n] = bd + s;
    }
}

// ---------------------------------------------------------------------------
// Persistent recurrence: 2-term FP16 wmma, 4-deep ring, single sync/stage,
// cross-barrier W prefetch, early-arrive barrier.
// 128 CTAs x 256 threads; block tile 64(M) x 64(N); warp tile 16x32.
// D f32[64][68] aliases ring slot 3.
// ---------------------------------------------------------------------------
__global__ __launch_bounds__(256, 1) void lstm_persist_kernel(
    const int* __restrict__ lengths, const int* __restrict__ tf_mask,
    float* __restrict__ enc_out){
    extern __shared__ __align__(16) char DS[];
    __half* RINGh = (__half*)DS;
    float*  Dsm   = (float*)(DS + 3*STAGE_BYTES);    // alias of slot 3
    const uint32_t ring_base = (uint32_t)__cvta_generic_to_shared(DS);
    const int tid = threadIdx.x, wid = tid >> 5;
    const int wm = wid & 3, wn = wid >> 2;           // warp rows wm*16, cols wn*32
    const int mt = blockIdx.x >> 6, nt = blockIdx.x & 63;

    // step-parameter helper (encoded inline below); W-only prefetch of step 0
    {
        const __half* W0 = g_Wenc;
        #pragma unroll
        for (int s = 0; s < 3; s++){
            const int k0 = s << 6;
            const uint32_t sb = ring_base + (uint32_t)s*STAGE_BYTES;
            #pragma unroll
            for (int i = 0; i < 2; i++){
                int c = tid + (i << 8);
                int r = c >> 3, q = c & 7;
                cp16(sb + (uint32_t)((OFF_BHh + r*PITCH + (q << 3))*2),
                     W0 + (size_t)(nt*64 + r)*KCAT + k0 + (q << 3));
            }
        }
    }

    for (int it = 0; it < 2*Tn; it++){
        const int mode = it >= Tn;
        const int step = mode ? it - Tn : it;
        const int pin = it & 1, pout = pin ^ 1;

        const __half* W; const float* bias; int K, ts;
        if (!mode){ W = g_Wenc; bias = g_benc; K = KCAT; ts = step; }
        else {
            int teach;
            if (step == 0){ teach = 1; ts = Tn - 1; }
            else          { teach = tf_mask[step - 1]; ts = step - 1; }
            if (teach){ W = g_Wdec;   bias = g_bdec;  K = KCAT; }
            else      { W = g_Wsum16; bias = g_b2dec; K = KHn;  }
        }
        const int nst = K >> 6;
        const __half* hHp = g_hH[pin];
        const __half* hLp = g_hL[pin];

        wmma::fragment<wmma::accumulator,16,16,16,float> acc[2];
        wmma::fill_fragment(acc[0], 0.0f);
        wmma::fill_fragment(acc[1], 0.0f);

        auto issueA = [&](int s){
            const int k0 = s << 6;
            const uint32_t sb = ring_base + (uint32_t)(s & 3)*STAGE_BYTES;
            #pragma unroll
            for (int i = 0; i < 4; i++){
                int c16 = tid + (i << 8);              // 0..1023
                int pl = c16 >> 9, r = (c16 >> 3) & 63, q = c16 & 7;
                int k = k0 + (q << 3);
                const __half* p;
                if (k < KHn) p = (pl ? hLp : hHp) + (size_t)(mt*64 + r)*KHn + k;
                else         p = (pl ? g_xL : g_xH) + ((size_t)ts*Bn + mt*64 + r)*In + (k - KHn);
                cp16(sb + (uint32_t)(((pl ? OFF_ALh : OFF_AHh) + r*PITCH + (q << 3))*2), p);
            }
        };
        auto issueW = [&](int s){
            const int k0 = s << 6;
            const uint32_t sb = ring_base + (uint32_t)(s & 3)*STAGE_BYTES;
            #pragma unroll
            for (int i = 0; i < 2; i++){
                int c = tid + (i << 8);                // 0..511
                int r = c >> 3, q = c & 7;
                cp16(sb + (uint32_t)((OFF_BHh + r*PITCH + (q << 3))*2),
                     W + (size_t)(nt*64 + r)*K + k0 + (q << 3));
            }
        };

        // A-parts of stages 0..2 (W parts pre-issued across the barrier);
        // commit 0 closes {W0,W1,W2,A0} — W1/W2 just complete early.
        issueA(0); asm volatile("cp.async.commit_group;\n");
        issueA(1); asm volatile("cp.async.commit_group;\n");
        issueA(2); asm volatile("cp.async.commit_group;\n");

        for (int s = 0; s < nst; s++){
            const int rem = nst - 1 - s;
            if (rem >= 2)      asm volatile("cp.async.wait_group 2;\n");
            else if (rem == 1) asm volatile("cp.async.wait_group 1;\n");
            else               asm volatile("cp.async.wait_group 0;\n");
            __syncthreads();   // stage s visible; all warps done with slot (s-1)&3
            if (s + 3 < nst){
                issueA(s + 3); issueW(s + 3);
                asm volatile("cp.async.commit_group;\n");
            }
            const __half* SB = RINGh + (size_t)(s & 3)*(STAGE_BYTES/2);
            #pragma unroll
            for (int kcl = 0; kcl < 4; kcl++){
                wmma::fragment<wmma::matrix_a,16,16,16,__half,wmma::row_major> aH, aL;
                wmma::fragment<wmma::matrix_b,16,16,16,__half,wmma::col_major> b0, b1;
                wmma::load_matrix_sync(aH, SB + OFF_AHh + (wm*16)*PITCH + kcl*16, PITCH);
                wmma::load_matrix_sync(aL, SB + OFF_ALh + (wm*16)*PITCH + kcl*16, PITCH);
                wmma::load_matrix_sync(b0, SB + OFF_BHh + (wn*32)*PITCH + kcl*16, PITCH);
                wmma::load_matrix_sync(b1, SB + OFF_BHh + (wn*32 + 16)*PITCH + kcl*16, PITCH);
                wmma::mma_sync(acc[0], aH, b0, acc[0]);
                wmma::mma_sync(acc[0], aL, b0, acc[0]);
                wmma::mma_sync(acc[1], aH, b1, acc[1]);
                wmma::mma_sync(acc[1], aL, b1, acc[1]);
            }
        }

        // ---- D -> smem slot 3 (sync first: nst=16's last stage reads slot 3) ----
        __syncthreads();
        wmma::store_matrix_sync(&Dsm[(wm*16)*68 + wn*32 +  0], acc[0], 68, wmma::mem_row_major);
        wmma::store_matrix_sync(&Dsm[(wm*16)*68 + wn*32 + 16], acc[1], 68, wmma::mem_row_major);
        __syncthreads();

        // ---- epilogue phase A: compute cell, write ONLY cross-CTA state ----
        const int ml = tid >> 2;
        const int m  = mt*64 + ml;
        const bool valid = mode ? true : (step < lengths[m]);
        float h2v[4], c2v[4], coldv[4];
        #pragma unroll
        for (int j = 0; j < 4; j++){
            const int ul = (tid & 3)*4 + j;
            const int u  = nt*16 + ul;
            float4 gv = *(const float4*)&Dsm[ml*68 + ul*4];   // i,f,g,o
            float iv = sigf(gv.x + bias[u]);
            float fv = sigf(gv.y + bias[Hn + u]);
            float gg = tanhf(gv.z + bias[2*Hn + u]);
            float ov = sigf(gv.w + bias[3*Hn + u]);
            const size_t idx = (size_t)m*Hn + u;
            coldv[j] = g_c[idx];
            c2v[j] = fmaf(fv, coldv[j], iv*gg);
            h2v[j] = ov * tanhf(c2v[j]);
            float hw = (!mode && !valid) ? g_hF[pin][idx] : h2v[j];
            g_hF[pout][idx] = hw;
            __half hh = __float2half(hw);
            g_hH[pout][idx] = hh;
            g_hL[pout][idx] = __float2half(hw - __half2float(hh));
        }
        __syncthreads();                       // all h writes issued
        if (tid == 0){
            __threadfence();                   // release
            atomicAdd(&g_arrive, 1u);
        }

        // ---- phase B (overlaps barrier poll): CTA-local writes + W prefetch ----
        #pragma unroll
        for (int j = 0; j < 4; j++){
            const int ul = (tid & 3)*4 + j;
            const int u  = nt*16 + ul;
            const size_t idx = (size_t)m*Hn + u;
            if (!mode){
                g_c[idx] = valid ? c2v[j] : coldv[j];
                enc_out[((size_t)m*Tn + step)*Hn + u] = valid ? h2v[j] : 0.0f;
            } else {
                g_c[idx] = c2v[j];
                g_dech[((size_t)step*Bn + m)*Hn + u] = h2v[j];
            }
        }
        if (it + 1 < 2*Tn){                    // W prefetch for next step, uncommitted
            const __half* Wn; int Kn;
            const int nit = it + 1;
            if (nit < Tn){ Wn = g_Wenc; Kn = KCAT; }
            else {
                int nstep = nit - Tn;
                int teach = (nstep == 0) ? 1 : tf_mask[nstep - 1];
                if (teach){ Wn = g_Wdec; Kn = KCAT; }
                else      { Wn = g_Wsum16; Kn = KHn; }
            }
            #pragma unroll
            for (int s = 0; s < 3; s++){
                const int k0 = s << 6;
                const uint32_t sb = ring_base + (uint32_t)s*STAGE_BYTES;
                #pragma unroll
                for (int i = 0; i < 2; i++){
                    int c = tid + (i << 8);
                    int r = c >> 3, q = c & 7;
                    cp16(sb + (uint32_t)((OFF_BHh + r*PITCH + (q << 3))*2),
                         Wn + (size_t)(nt*64 + r)*Kn + k0 + (q << 3));
                }
            }
        }
        if (tid == 0){
            const unsigned goal = (unsigned)(it + 1) * gridDim.x;
            while (*((volatile unsigned*)&g_arrive) < goal) {}
        }
        __syncthreads();                       // release all threads
    }
}

// ---------------------------------------------------------------------------
// Final output projection: out[b][s][:] = dech[s][b][:] @ lin_W^T + lin_b
// ---------------------------------------------------------------------------
__global__ __launch_bounds__(256, 1) void final_gemm_kernel(
    const float* __restrict__ linW, const float* __restrict__ linb,
    float* __restrict__ out){
    const int tid = threadIdx.x;
    const int tx = tid & 15, ty = tid >> 4;
    const int r0 = blockIdx.x << 6;
    const int n0 = blockIdx.y << 6;

    __shared__ __align__(16) float Asx[16][72];
    __shared__ __align__(16) float Wsx[16][72];
    float acc[4][4] = {};

    const int lrow = tid >> 2, lc4 = tid & 3;
    const float* aptr = g_dech + (size_t)(r0 + lrow)*Hn;
    const float* wptr = linW + (size_t)(n0 + lrow)*Hn;

    for (int k0 = 0; k0 < Hn; k0 += 16){
        const int k = k0 + lc4*4;
        float4 wv = *(const float4*)(wptr + k);
        float4 av = *(const float4*)(aptr + k);
        __syncthreads();
        Wsx[lc4*4 + 0][lrow] = wv.x; Wsx[lc4*4 + 1][lrow] = wv.y;
        Wsx[lc4*4 + 2][lrow] = wv.z; Wsx[lc4*4 + 3][lrow] = wv.w;
        Asx[lc4*4 + 0][lrow] = av.x; Asx[lc4*4 + 1][lrow] = av.y;
        Asx[lc4*4 + 2][lrow] = av.z; Asx[lc4*4 + 3][lrow] = av.w;
        __syncthreads();
        #pragma unroll
        for (int kk = 0; kk < 16; kk++){
            float4 a4 = *(const float4*)&Asx[kk][ty*4];
            float4 w4 = *(const float4*)&Wsx[kk][tx*4];
            float a[4] = {a4.x, a4.y, a4.z, a4.w};
            float w[4] = {w4.x, w4.y, w4.z, w4.w};
            #pragma unroll
            for (int i = 0; i < 4; i++)
                #pragma unroll
                for (int j = 0; j < 4; j++)
                    acc[i][j] = fmaf(a[i], w[j], acc[i][j]);
        }
    }

    #pragma unroll
    for (int r = 0; r < 4; r++){
        int rr = r0 + ty*4 + r;
        int s = rr >> 7;
        int b = rr & 127;
        int n = n0 + tx*4;
        float4 o;
        o.x = acc[r][0] + linb[n + 0];
        o.y = acc[r][1] + linb[n + 1];
        o.z = acc[r][2] + linb[n + 2];
        o.w = acc[r][3] + linb[n + 3];
        *(float4*)(out + ((size_t)b*Tn + s)*In + n) = o;
    }
}

// ---------------------------------------------------------------------------
// kernel_launch — 9 graph nodes. No __device__ symbol passed from host.
// Inputs: x_input, enc_Wih, enc_Whh, enc_bih, enc_bhh, dec_Wih, dec_Whh,
//         dec_bih, dec_bhh, lin_W, lin_b, lengths, tf_mask.
// Output: [outputs (B*T*I) | encoder_output (B*T*H)] float32.
// ---------------------------------------------------------------------------
extern "C" void kernel_launch(void* const* d_in, const int* in_sizes, int n_in,
                              void* d_out, int out_size){
    const float* x       = (const float*)d_in[0];
    const float* eWih    = (const float*)d_in[1];
    const float* eWhh    = (const float*)d_in[2];
    const float* ebih    = (const float*)d_in[3];
    const float* ebhh    = (const float*)d_in[4];
    const float* dWih    = (const float*)d_in[5];
    const float* dWhh    = (const float*)d_in[6];
    const float* dbih    = (const float*)d_in[7];
    const float* dbhh    = (const float*)d_in[8];
    const float* linW    = (const float*)d_in[9];
    const float* linb    = (const float*)d_in[10];
    const int*   lengths = (const int*)d_in[11];
    const int*   tfm     = (const int*)d_in[12];
    float* out = (float*)d_out;
    float* enc_out = out + (size_t)Bn*Tn*In;

    cudaFuncSetAttribute(lstm_persist_kernel,
                         cudaFuncAttributeMaxDynamicSharedMemorySize, SMEM_BYTES);

    zero_state_kernel<<<(BHn + 255)/256, 256>>>();
    pack_w_kernel<<<(int)(((size_t)Gn*KCAT + 255)/256), 256>>>(eWhh, eWih, 0, KCAT);
    pack_w_kernel<<<(int)(((size_t)Gn*KCAT + 255)/256), 256>>>(dWhh, dWih, 1, KCAT);
    build_wsum_kernel<<<Gn, 256>>>(dWhh, dWih, linW);
    pack_w_kernel<<<(int)(((size_t)Gn*KHn + 255)/256), 256>>>((const float*)0, (const float*)0, 2, KHn);
    build_bias_kernel<<<(Gn + 255)/256, 256>>>(ebih, ebhh, dbih, dbhh, dWih, linb);
    pack_x_kernel<<<(int)(((size_t)Tn*Bn*In + 255)/256), 256>>>(x);

    lstm_persist_kernel<<<128, 256, SMEM_BYTES>>>(lengths, tfm, enc_out);

    final_gemm_kernel<<<dim3((Tn*Bn)/64, In/64), 256>>>(linW, linb, out);
}

// round 14
// speedup vs baseline: 5.0210x; 1.4986x over previous
#include <cuda_runtime.h>
#include <cuda_fp16.h>
#include <math.h>
#include <stdint.h>
#include <mma.h>
using namespace nvcuda;

#define Bn 128
#define Tn 512
#define In 128
#define Hn 1024
#define Gn 4096
#define KHn 1024
#define KCAT 1152
#define BHn (Bn*Hn)

// Stage (BK=128): A[64][136] + B[64][136] half = 34816 B; ring of 4.
#define PITCH 136
#define OFF_Ah 0
#define OFF_Bh 8704             // 64*136 halves
#define STAGE_BYTES 34816
#define SMEM_BYTES (4*STAGE_BYTES)   // 139264 B

// ---------------------------------------------------------------------------
// Static device scratch — referenced ONLY from device code (GB300/ATS trap:
// host-passing a __device__ symbol silently uses the host shadow address)
// ---------------------------------------------------------------------------
__device__ __half g_Wenc[(size_t)Gn*KCAT];     // fp16, [n][k]
__device__ __half g_Wdec[(size_t)Gn*KCAT];
__device__ __half g_Wsum16[(size_t)Gn*KHn];
__device__ float  g_wsum[(size_t)Gn*KHn];
__device__ __half g_xH[(size_t)Tn*Bn*In];      // [t][m][k] fp16
__device__ __half g_hH[2][BHn];                // [m][h] fp16
__device__ float  g_hF[2][BHn];
__device__ float  g_c[BHn];
__device__ float  g_dech[(size_t)Tn*BHn];      // [s][b][h]
__device__ float  g_benc[Gn], g_bdec[Gn], g_b2dec[Gn];
__device__ unsigned g_arrive;

__device__ __forceinline__ float sigf(float x){ return 1.f/(1.f+__expf(-x)); }
__device__ __forceinline__ void cp16(uint32_t dst, const void* src){
    asm volatile("cp.async.cg.shared.global [%0],[%1],16;\n" :: "r"(dst), "l"(src));
}

// ---------------------------------------------------------------------------
// Prep kernels (elementwise)
// ---------------------------------------------------------------------------
__global__ void zero_state_kernel(){
    int i = blockIdx.x*blockDim.x + threadIdx.x;
    if (i == 0) g_arrive = 0u;
    if (i < BHn){
        g_hH[0][i] = __float2half(0.f);
        g_hF[0][i] = 0.f;
        g_c[i] = 0.f;
    }
}

// which: 0 enc, 1 dec (src harness Whh/Wih, K=KCAT); 2 sum (src g_wsum, K=KHn)
// dst[n][k]; packed col n -> unit n>>2, gate n&3 (src row = gate*H + unit)
__global__ void pack_w_kernel(const float* __restrict__ Whh,
                              const float* __restrict__ Wih,
                              int which, int K){
    size_t idx = (size_t)blockIdx.x*256 + threadIdx.x;
    if (idx >= (size_t)Gn*K) return;
    int n = (int)(idx / K), k = (int)(idx - (size_t)n*K);
    int srcrow = (n & 3)*Hn + (n >> 2);
    float v;
    if (which == 2)
        v = g_wsum[(size_t)srcrow*KHn + k];
    else
        v = (k < KHn) ? Whh[(size_t)srcrow*KHn + k] : Wih[(size_t)srcrow*In + (k - KHn)];
    __half* P = (which == 0) ? g_Wenc : (which == 1) ? g_Wdec : g_Wsum16;
    P[idx] = __float2half(v);
}

__global__ void pack_x_kernel(const float* __restrict__ x){
    size_t idx = (size_t)blockIdx.x*256 + threadIdx.x;
    if (idx >= (size_t)Tn*Bn*In) return;
    int k = (int)(idx & (In - 1));
    int m = (int)((idx >> 7) & (Bn - 1));
    int t = (int)(idx >> 14);
    g_xH[idx] = __float2half(x[((size_t)m*Tn + t)*In + k]);
}

__global__ __launch_bounds__(256) void build_wsum_kernel(
    const float* __restrict__ Whh, const float* __restrict__ Wih,
    const float* __restrict__ linW){
    const int n = blockIdx.x;
    __shared__ float wr[In];
    if (threadIdx.x < In) wr[threadIdx.x] = Wih[n*In + threadIdx.x];
    __syncthreads();
    #pragma unroll
    for (int c = 0; c < 4; c++){
        int k = threadIdx.x + 256*c;
        float s = 0.0f;
        #pragma unroll 8
        for (int j = 0; j < In; j++) s = fmaf(wr[j], linW[j*Hn + k], s);
        g_wsum[(size_t)n*KHn + k] = Whh[(size_t)n*KHn + k] + s;
    }
}

__global__ void build_bias_kernel(const float* __restrict__ ebih, const float* __restrict__ ebhh,
                                  const float* __restrict__ dbih, const float* __restrict__ dbhh,
                                  const float* __restrict__ dWih, const float* __restrict__ linb){
    int n = blockIdx.x*blockDim.x + threadIdx.x;
    if (n < Gn){
        g_benc[n] = ebih[n] + ebhh[n];
        float bd = dbih[n] + dbhh[n];
        g_bdec[n] = bd;
        float s = 0.0f;
        #pragma unroll 8
        for (int j = 0; j < In; j++) s = fmaf(dWih[n*In + j], linb[j], s);
        g_b2dec[n] = bd + s;
    }
}

// ---------------------------------------------------------------------------
// Persistent recurrence: 1-term FP16 wmma, BK=128, 4-deep ring, single
// sync/stage, cross-barrier W prefetch, early-arrive barrier.
// 128 CTAs x 256 threads; block tile 64(M) x 64(N); warp tile 16x32.
// D f32[64][68] aliases ring slot 3.
// ---------------------------------------------------------------------------
__global__ __launch_bounds__(256, 1) void lstm_persist_kernel(
    const int* __restrict__ lengths, const int* __restrict__ tf_mask,
    float* __restrict__ enc_out){
    extern __shared__ __align__(16) char DS[];
    __half* RINGh = (__half*)DS;
    float*  Dsm   = (float*)(DS + 3*STAGE_BYTES);    // alias of slot 3
    const uint32_t ring_base = (uint32_t)__cvta_generic_to_shared(DS);
    const int tid = threadIdx.x, wid = tid >> 5;
    const int wm = wid & 3, wn = wid >> 2;           // warp rows wm*16, cols wn*32
    const int mt = blockIdx.x >> 6, nt = blockIdx.x & 63;

    // W-only prefetch of step 0, stages 0..2 (uncommitted)
    {
        #pragma unroll
        for (int s = 0; s < 3; s++){
            const int k0 = s << 7;
            const uint32_t sb = ring_base + (uint32_t)s*STAGE_BYTES;
            #pragma unroll
            for (int i = 0; i < 4; i++){
                int c = tid + (i << 8);
                int r = c >> 4, q = c & 15;
                cp16(sb + (uint32_t)((OFF_Bh + r*PITCH + (q << 3))*2),
                     g_Wenc + (size_t)(nt*64 + r)*KCAT + k0 + (q << 3));
            }
        }
    }

    for (int it = 0; it < 2*Tn; it++){
        const int mode = it >= Tn;
        const int step = mode ? it - Tn : it;
        const int pin = it & 1, pout = pin ^ 1;

        const __half* W; const float* bias; int K, ts;
        if (!mode){ W = g_Wenc; bias = g_benc; K = KCAT; ts = step; }
        else {
            int teach;
            if (step == 0){ teach = 1; ts = Tn - 1; }
            else          { teach = tf_mask[step - 1]; ts = step - 1; }
            if (teach){ W = g_Wdec;   bias = g_bdec;  K = KCAT; }
            else      { W = g_Wsum16; bias = g_b2dec; K = KHn;  }
        }
        const int nst = K >> 7;                 // 9 (KCAT) or 8 (KHn)
        const __half* hHp = g_hH[pin];

        wmma::fragment<wmma::accumulator,16,16,16,float> acc[2];
        wmma::fill_fragment(acc[0], 0.0f);
        wmma::fill_fragment(acc[1], 0.0f);

        auto issueA = [&](int s){
            const int k0 = s << 7;
            const uint32_t sb = ring_base + (uint32_t)(s & 3)*STAGE_BYTES;
            #pragma unroll
            for (int i = 0; i < 4; i++){
                int c = tid + (i << 8);                // 0..1023
                int r = c >> 4, q = c & 15;
                int k = k0 + (q << 3);
                const __half* p;
                if (k < KHn) p = hHp + (size_t)(mt*64 + r)*KHn + k;
                else         p = g_xH + ((size_t)ts*Bn + mt*64 + r)*In + (k - KHn);
                cp16(sb + (uint32_t)((OFF_Ah + r*PITCH + (q << 3))*2), p);
            }
        };
        auto issueW = [&](int s){
            const int k0 = s << 7;
            const uint32_t sb = ring_base + (uint32_t)(s & 3)*STAGE_BYTES;
            #pragma unroll
            for (int i = 0; i < 4; i++){
                int c = tid + (i << 8);
                int r = c >> 4, q = c & 15;
                cp16(sb + (uint32_t)((OFF_Bh + r*PITCH + (q << 3))*2),
                     W + (size_t)(nt*64 + r)*K + k0 + (q << 3));
            }
        };

        // A-parts of stages 0..2 (W parts pre-issued across the barrier)
        issueA(0); asm volatile("cp.async.commit_group;\n");
        issueA(1); asm volatile("cp.async.commit_group;\n");
        issueA(2); asm volatile("cp.async.commit_group;\n");

        for (int s = 0; s < nst; s++){
            const int rem = nst - 1 - s;
            if (rem >= 2)      asm volatile("cp.async.wait_group 2;\n");
            else if (rem == 1) asm volatile("cp.async.wait_group 1;\n");
            else               asm volatile("cp.async.wait_group 0;\n");
            __syncthreads();   // stage s visible; all warps done with slot (s-1)&3
            if (s + 3 < nst){
                issueA(s + 3); issueW(s + 3);
                asm volatile("cp.async.commit_group;\n");
            }
            const __half* SB = RINGh + (size_t)(s & 3)*(STAGE_BYTES/2);
            #pragma unroll
            for (int kcl = 0; kcl < 8; kcl++){
                wmma::fragment<wmma::matrix_a,16,16,16,__half,wmma::row_major> aH;
                wmma::fragment<wmma::matrix_b,16,16,16,__half,wmma::col_major> b0, b1;
                wmma::load_matrix_sync(aH, SB + OFF_Ah + (wm*16)*PITCH + kcl*16, PITCH);
                wmma::load_matrix_sync(b0, SB + OFF_Bh + (wn*32)*PITCH + kcl*16, PITCH);
                wmma::load_matrix_sync(b1, SB + OFF_Bh + (wn*32 + 16)*PITCH + kcl*16, PITCH);
                wmma::mma_sync(acc[0], aH, b0, acc[0]);
                wmma::mma_sync(acc[1], aH, b1, acc[1]);
            }
        }

        // ---- D -> smem slot 3 ----
        __syncthreads();
        wmma::store_matrix_sync(&Dsm[(wm*16)*68 + wn*32 +  0], acc[0], 68, wmma::mem_row_major);
        wmma::store_matrix_sync(&Dsm[(wm*16)*68 + wn*32 + 16], acc[1], 68, wmma::mem_row_major);
        __syncthreads();

        // ---- epilogue phase A: compute cell, write ONLY cross-CTA state ----
        const int ml = tid >> 2;
        const int m  = mt*64 + ml;
        const bool valid = mode ? true : (step < lengths[m]);
        float h2v[4], c2v[4], coldv[4];
        #pragma unroll
        for (int j = 0; j < 4; j++){
            const int ul = (tid & 3)*4 + j;
            const int u  = nt*16 + ul;
            float4 gv = *(const float4*)&Dsm[ml*68 + ul*4];   // i,f,g,o
            float iv = sigf(gv.x + bias[u]);
            float fv = sigf(gv.y + bias[Hn + u]);
            float gg = tanhf(gv.z + bias[2*Hn + u]);
            float ov = sigf(gv.w + bias[3*Hn + u]);
            const size_t idx = (size_t)m*Hn + u;
            coldv[j] = g_c[idx];
            c2v[j] = fmaf(fv, coldv[j], iv*gg);
            h2v[j] = ov * tanhf(c2v[j]);
            float hw = (!mode && !valid) ? g_hF[pin][idx] : h2v[j];
            g_hF[pout][idx] = hw;
            g_hH[pout][idx] = __float2half(hw);
        }
        __syncthreads();                       // all h writes issued
        if (tid == 0){
            __threadfence();                   // release
            atomicAdd(&g_arrive, 1u);
        }

        // ---- phase B (overlaps barrier poll): CTA-local writes + W prefetch ----
        #pragma unroll
        for (int j = 0; j < 4; j++){
            const int ul = (tid & 3)*4 + j;
            const int u  = nt*16 + ul;
            const size_t idx = (size_t)m*Hn + u;
            if (!mode){
                g_c[idx] = valid ? c2v[j] : coldv[j];
                enc_out[((size_t)m*Tn + step)*Hn + u] = valid ? h2v[j] : 0.0f;
            } else {
                g_c[idx] = c2v[j];
                g_dech[((size_t)step*Bn + m)*Hn + u] = h2v[j];
            }
        }
        if (it + 1 < 2*Tn){                    // next-step W prefetch, uncommitted
            const __half* Wn; int Kn;
            const int nit = it + 1;
            if (nit < Tn){ Wn = g_Wenc; Kn = KCAT; }
            else {
                int nstep = nit - Tn;
                int teach = (nstep == 0) ? 1 : tf_mask[nstep - 1];
                if (teach){ Wn = g_Wdec; Kn = KCAT; }
                else      { Wn = g_Wsum16; Kn = KHn; }
            }
            #pragma unroll
            for (int s = 0; s < 3; s++){
                const int k0 = s << 7;
                const uint32_t sb = ring_base + (uint32_t)s*STAGE_BYTES;
                #pragma unroll
                for (int i = 0; i < 4; i++){
                    int c = tid + (i << 8);
                    int r = c >> 4, q = c & 15;
                    cp16(sb + (uint32_t)((OFF_Bh + r*PITCH + (q << 3))*2),
                         Wn + (size_t)(nt*64 + r)*Kn + k0 + (q << 3));
                }
            }
        }
        if (tid == 0){
            const unsigned goal = (unsigned)(it + 1) * gridDim.x;
            while (*((volatile unsigned*)&g_arrive) < goal) {}
        }
        __syncthreads();                       // release all threads
    }
}

// ---------------------------------------------------------------------------
// Final output projection: out[b][s][:] = dech[s][b][:] @ lin_W^T + lin_b
// ---------------------------------------------------------------------------
__global__ __launch_bounds__(256, 1) void final_gemm_kernel(
    const float* __restrict__ linW, const float* __restrict__ linb,
    float* __restrict__ out){
    const int tid = threadIdx.x;
    const int tx = tid & 15, ty = tid >> 4;
    const int r0 = blockIdx.x << 6;
    const int n0 = blockIdx.y << 6;

    __shared__ __align__(16) float Asx[16][72];
    __shared__ __align__(16) float Wsx[16][72];
    float acc[4][4] = {};

    const int lrow = tid >> 2, lc4 = tid & 3;
    const float* aptr = g_dech + (size_t)(r0 + lrow)*Hn;
    const float* wptr = linW + (size_t)(n0 + lrow)*Hn;

    for (int k0 = 0; k0 < Hn; k0 += 16){
        const int k = k0 + lc4*4;
        float4 wv = *(const float4*)(wptr + k);
        float4 av = *(const float4*)(aptr + k);
        __syncthreads();
        Wsx[lc4*4 + 0][lrow] = wv.x; Wsx[lc4*4 + 1][lrow] = wv.y;
        Wsx[lc4*4 + 2][lrow] = wv.z; Wsx[lc4*4 + 3][lrow] = wv.w;
        Asx[lc4*4 + 0][lrow] = av.x; Asx[lc4*4 + 1][lrow] = av.y;
        Asx[lc4*4 + 2][lrow] = av.z; Asx[lc4*4 + 3][lrow] = av.w;
        __syncthreads();
        #pragma unroll
        for (int kk = 0; kk < 16; kk++){
            float4 a4 = *(const float4*)&Asx[kk][ty*4];
            float4 w4 = *(const float4*)&Wsx[kk][tx*4];
            float a[4] = {a4.x, a4.y, a4.z, a4.w};
            float w[4] = {w4.x, w4.y, w4.z, w4.w};
            #pragma unroll
            for (int i = 0; i < 4; i++)
                #pragma unroll
                for (int j = 0; j < 4; j++)
                    acc[i][j] = fmaf(a[i], w[j], acc[i][j]);
        }
    }

    #pragma unroll
    for (int r = 0; r < 4; r++){
        int rr = r0 + ty*4 + r;
        int s = rr >> 7;
        int b = rr & 127;
        int n = n0 + tx*4;
        float4 o;
        o.x = acc[r][0] + linb[n + 0];
        o.y = acc[r][1] + linb[n + 1];
        o.z = acc[r][2] + linb[n + 2];
        o.w = acc[r][3] + linb[n + 3];
        *(float4*)(out + ((size_t)b*Tn + s)*In + n) = o;
    }
}

// ---------------------------------------------------------------------------
// kernel_launch — 9 graph nodes. No __device__ symbol passed from host.
// Inputs: x_input, enc_Wih, enc_Whh, enc_bih, enc_bhh, dec_Wih, dec_Whh,
//         dec_bih, dec_bhh, lin_W, lin_b, lengths, tf_mask.
// Output: [outputs (B*T*I) | encoder_output (B*T*H)] float32.
// ---------------------------------------------------------------------------
extern "C" void kernel_launch(void* const* d_in, const int* in_sizes, int n_in,
                              void* d_out, int out_size){
    const float* x       = (const float*)d_in[0];
    const float* eWih    = (const float*)d_in[1];
    const float* eWhh    = (const float*)d_in[2];
    const float* ebih    = (const float*)d_in[3];
    const float* ebhh    = (const float*)d_in[4];
    const float* dWih    = (const float*)d_in[5];
    const float* dWhh    = (const float*)d_in[6];
    const float* dbih    = (const float*)d_in[7];
    const float* dbhh    = (const float*)d_in[8];
    const float* linW    = (const float*)d_in[9];
    const float* linb    = (const float*)d_in[10];
    const int*   lengths = (const int*)d_in[11];
    const int*   tfm     = (const int*)d_in[12];
    float* out = (float*)d_out;
    float* enc_out = out + (size_t)Bn*Tn*In;

    cudaFuncSetAttribute(lstm_persist_kernel,
                         cudaFuncAttributeMaxDynamicSharedMemorySize, SMEM_BYTES);

    zero_state_kernel<<<(BHn + 255)/256, 256>>>();
    pack_w_kernel<<<(int)(((size_t)Gn*KCAT + 255)/256), 256>>>(eWhh, eWih, 0, KCAT);
    pack_w_kernel<<<(int)(((size_t)Gn*KCAT + 255)/256), 256>>>(dWhh, dWih, 1, KCAT);
    build_wsum_kernel<<<Gn, 256>>>(dWhh, dWih, linW);
    pack_w_kernel<<<(int)(((size_t)Gn*KHn + 255)/256), 256>>>((const float*)0, (const float*)0, 2, KHn);
    build_bias_kernel<<<(Gn + 255)/256, 256>>>(ebih, ebhh, dbih, dbhh, dWih, linb);
    pack_x_kernel<<<(int)(((size_t)Tn*Bn*In + 255)/256), 256>>>(x);

    lstm_persist_kernel<<<128, 256, SMEM_BYTES>>>(lengths, tfm, enc_out);

    final_gemm_kernel<<<dim3((Tn*Bn)/64, In/64), 256>>>(linW, linb, out);
}

// round 16
// speedup vs baseline: 5.9457x; 1.1842x over previous
#include <cuda_runtime.h>
#include <cuda_fp16.h>
#include <math.h>
#include <stdint.h>
#include <mma.h>
using namespace nvcuda;

#define Bn 128
#define Tn 512
#define In 128
#define Hn 1024
#define Gn 4096
#define KHn 1024
#define KCAT 1152
#define BHn (Bn*Hn)

// Stage (BK=128): A[64][136] + B[64][136] half = 34816 B; ring of 4.
#define PITCH 136
#define OFF_Ah 0
#define OFF_Bh 8704             // 64*136 halves
#define STAGE_BYTES 34816
#define SMEM_BYTES (4*STAGE_BYTES)   // 139264 B

// ---------------------------------------------------------------------------
// Static device scratch — referenced ONLY from device code (GB300/ATS trap:
// host-passing a __device__ symbol silently uses the host shadow address)
// ---------------------------------------------------------------------------
__device__ __half g_Wenc[(size_t)Gn*KCAT];     // fp16, [n][k]
__device__ __half g_Wdec[(size_t)Gn*KCAT];
__device__ __half g_Wsum16[(size_t)Gn*KHn];
__device__ __half g_linw16[(size_t)In*Hn];     // lin_W fp16, [n][k]
__device__ float  g_wsum[(size_t)Gn*KHn];
__device__ __half g_xH[(size_t)Tn*Bn*In];      // [t][m][k] fp16
__device__ __half g_hH[2][BHn];                // [m][h] fp16
__device__ float  g_c[BHn];
__device__ __half g_dech16[(size_t)Tn*BHn];    // [s][b][h] fp16
__device__ float  g_benc[Gn], g_bdec[Gn], g_b2dec[Gn];
__device__ unsigned g_arrive;

__device__ __forceinline__ float sigf(float x){ return 1.f/(1.f+__expf(-x)); }
__device__ __forceinline__ void cp16(uint32_t dst, const void* src){
    asm volatile("cp.async.cg.shared.global [%0],[%1],16;\n" :: "r"(dst), "l"(src));
}

// ---------------------------------------------------------------------------
// Prep kernels (elementwise)
// ---------------------------------------------------------------------------
__global__ void zero_state_kernel(){
    int i = blockIdx.x*blockDim.x + threadIdx.x;
    if (i == 0) g_arrive = 0u;
    if (i < BHn){
        g_hH[0][i] = __float2half(0.f);
        g_c[i] = 0.f;
    }
}

// which: 0 enc, 1 dec (src harness Whh/Wih, K=KCAT); 2 sum (src g_wsum, K=KHn)
// dst[n][k]; packed col n -> unit n>>2, gate n&3 (src row = gate*H + unit)
__global__ void pack_w_kernel(const float* __restrict__ Whh,
                              const float* __restrict__ Wih,
                              int which, int K){
    size_t idx = (size_t)blockIdx.x*256 + threadIdx.x;
    if (idx >= (size_t)Gn*K) return;
    int n = (int)(idx / K), k = (int)(idx - (size_t)n*K);
    int srcrow = (n & 3)*Hn + (n >> 2);
    float v;
    if (which == 2)
        v = g_wsum[(size_t)srcrow*KHn + k];
    else
        v = (k < KHn) ? Whh[(size_t)srcrow*KHn + k] : Wih[(size_t)srcrow*In + (k - KHn)];
    __half* P = (which == 0) ? g_Wenc : (which == 1) ? g_Wdec : g_Wsum16;
    P[idx] = __float2half(v);
}

__global__ void pack_x_kernel(const float* __restrict__ x){
    size_t idx = (size_t)blockIdx.x*256 + threadIdx.x;
    if (idx >= (size_t)Tn*Bn*In) return;
    int k = (int)(idx & (In - 1));
    int m = (int)((idx >> 7) & (Bn - 1));
    int t = (int)(idx >> 14);
    g_xH[idx] = __float2half(x[((size_t)m*Tn + t)*In + k]);
}

__global__ void pack_linw_kernel(const float* __restrict__ linW){
    int i = blockIdx.x*256 + threadIdx.x;
    if (i < In*Hn) g_linw16[i] = __float2half(linW[i]);   // already [n][k]
}

__global__ __launch_bounds__(256) void build_wsum_kernel(
    const float* __restrict__ Whh, const float* __restrict__ Wih,
    const float* __restrict__ linW){
    const int n = blockIdx.x;
    __shared__ float wr[In];
    if (threadIdx.x < In) wr[threadIdx.x] = Wih[n*In + threadIdx.x];
    __syncthreads();
    #pragma unroll
    for (int c = 0; c < 4; c++){
        int k = threadIdx.x + 256*c;
        float s = 0.0f;
        #pragma unroll 8
        for (int j = 0; j < In; j++) s = fmaf(wr[j], linW[j*Hn + k], s);
        g_wsum[(size_t)n*KHn + k] = Whh[(size_t)n*KHn + k] + s;
    }
}

__global__ void build_bias_kernel(const float* __restrict__ ebih, const float* __restrict__ ebhh,
                                  const float* __restrict__ dbih, const float* __restrict__ dbhh,
                                  const float* __restrict__ dWih, const float* __restrict__ linb){
    int n = blockIdx.x*blockDim.x + threadIdx.x;
    if (n < Gn){
        g_benc[n] = ebih[n] + ebhh[n];
        float bd = dbih[n] + dbhh[n];
        g_bdec[n] = bd;
        float s = 0.0f;
        #pragma unroll 8
        for (int j = 0; j < In; j++) s = fmaf(dWih[n*In + j], linb[j], s);
        g_b2dec[n] = bd + s;
    }
}

// ---------------------------------------------------------------------------
// Persistent recurrence: 1-term FP16 wmma, BK=128, 4-deep ring, single
// sync/stage, cross-barrier W prefetch, early-arrive barrier.
// 128 CTAs x 256 threads; block tile 64(M) x 64(N); warp tile 16x32.
// D f32[64][68] aliases ring slot 3.
// ---------------------------------------------------------------------------
__global__ __launch_bounds__(256, 1) void lstm_persist_kernel(
    const int* __restrict__ lengths, const int* __restrict__ tf_mask,
    float* __restrict__ enc_out){
    extern __shared__ __align__(16) char DS[];
    __half* RINGh = (__half*)DS;
    float*  Dsm   = (float*)(DS + 3*STAGE_BYTES);    // alias of slot 3
    const uint32_t ring_base = (uint32_t)__cvta_generic_to_shared(DS);
    const int tid = threadIdx.x, wid = tid >> 5;
    const int wm = wid & 3, wn = wid >> 2;           // warp rows wm*16, cols wn*32
    const int mt = blockIdx.x >> 6, nt = blockIdx.x & 63;

    // fixed per-thread epilogue coordinates
    const int ml = tid >> 2;
    const int m  = mt*64 + ml;
    const int ubase = nt*16 + (tid & 3)*4;           // 4 consecutive units
    const size_t idx0 = (size_t)m*Hn + ubase;

    // W-only prefetch of step 0, stages 0..2 (uncommitted)
    #pragma unroll
    for (int s = 0; s < 3; s++){
        const int k0 = s << 7;
        const uint32_t sb = ring_base + (uint32_t)s*STAGE_BYTES;
        #pragma unroll
        for (int i = 0; i < 4; i++){
            int c = tid + (i << 8);
            int r = c >> 4, q = c & 15;
            cp16(sb + (uint32_t)((OFF_Bh + r*PITCH + (q << 3))*2),
                 g_Wenc + (size_t)(nt*64 + r)*KCAT + k0 + (q << 3));
        }
    }

    for (int it = 0; it < 2*Tn; it++){
        const int mode = it >= Tn;
        const int step = mode ? it - Tn : it;
        const int pin = it & 1, pout = pin ^ 1;

        // prefetch cell state early (CTA-private, L1-resident)
        const float4 cold4 = *(const float4*)&g_c[idx0];

        const __half* W; const float* bias; int K, ts;
        if (!mode){ W = g_Wenc; bias = g_benc; K = KCAT; ts = step; }
        else {
            int teach;
            if (step == 0){ teach = 1; ts = Tn - 1; }
            else          { teach = tf_mask[step - 1]; ts = step - 1; }
            if (teach){ W = g_Wdec;   bias = g_bdec;  K = KCAT; }
            else      { W = g_Wsum16; bias = g_b2dec; K = KHn;  }
        }
        const int nst = K >> 7;                 // 9 (KCAT) or 8 (KHn)
        const __half* hHp = g_hH[pin];

        wmma::fragment<wmma::accumulator,16,16,16,float> acc[2];
        wmma::fill_fragment(acc[0], 0.0f);
        wmma::fill_fragment(acc[1], 0.0f);

        auto issueA = [&](int s){
            const int k0 = s << 7;
            const uint32_t sb = ring_base + (uint32_t)(s & 3)*STAGE_BYTES;
            #pragma unroll
            for (int i = 0; i < 4; i++){
                int c = tid + (i << 8);                // 0..1023
                int r = c >> 4, q = c & 15;
                int k = k0 + (q << 3);
                const __half* p;
                if (k < KHn) p = hHp + (size_t)(mt*64 + r)*KHn + k;
                else         p = g_xH + ((size_t)ts*Bn + mt*64 + r)*In + (k - KHn);
                cp16(sb + (uint32_t)((OFF_Ah + r*PITCH + (q << 3))*2), p);
            }
        };
        auto issueW = [&](int s){
            const int k0 = s << 7;
            const uint32_t sb = ring_base + (uint32_t)(s & 3)*STAGE_BYTES;
            #pragma unroll
            for (int i = 0; i < 4; i++){
                int c = tid + (i << 8);
                int r = c >> 4, q = c & 15;
                cp16(sb + (uint32_t)((OFF_Bh + r*PITCH + (q << 3))*2),
                     W + (size_t)(nt*64 + r)*K + k0 + (q << 3));
            }
        };

        // A-parts of stages 0..2 (W parts pre-issued across the barrier)
        issueA(0); asm volatile("cp.async.commit_group;\n");
        issueA(1); asm volatile("cp.async.commit_group;\n");
        issueA(2); asm volatile("cp.async.commit_group;\n");

        for (int s = 0; s < nst; s++){
            const int rem = nst - 1 - s;
            if (rem >= 2)      asm volatile("cp.async.wait_group 2;\n");
            else if (rem == 1) asm volatile("cp.async.wait_group 1;\n");
            else               asm volatile("cp.async.wait_group 0;\n");
            __syncthreads();   // stage s visible; all warps done with slot (s-1)&3
            if (s + 3 < nst){
                issueA(s + 3); issueW(s + 3);
                asm volatile("cp.async.commit_group;\n");
            }
            const __half* SB = RINGh + (size_t)(s & 3)*(STAGE_BYTES/2);
            #pragma unroll
            for (int kcl = 0; kcl < 8; kcl++){
                wmma::fragment<wmma::matrix_a,16,16,16,__half,wmma::row_major> aH;
                wmma::fragment<wmma::matrix_b,16,16,16,__half,wmma::col_major> b0, b1;
                wmma::load_matrix_sync(aH, SB + OFF_Ah + (wm*16)*PITCH + kcl*16, PITCH);
                wmma::load_matrix_sync(b0, SB + OFF_Bh + (wn*32)*PITCH + kcl*16, PITCH);
                wmma::load_matrix_sync(b1, SB + OFF_Bh + (wn*32 + 16)*PITCH + kcl*16, PITCH);
                wmma::mma_sync(acc[0], aH, b0, acc[0]);
                wmma::mma_sync(acc[1], aH, b1, acc[1]);
            }
        }

        // ---- D -> smem slot 3 (extra sync only if last stage used slot 3) ----
        if (nst == 8) __syncthreads();
        wmma::store_matrix_sync(&Dsm[(wm*16)*68 + wn*32 +  0], acc[0], 68, wmma::mem_row_major);
        wmma::store_matrix_sync(&Dsm[(wm*16)*68 + wn*32 + 16], acc[1], 68, wmma::mem_row_major);
        __syncthreads();

        // ---- epilogue phase A: compute cell, write ONLY cross-CTA state ----
        const bool valid = mode ? true : (step < lengths[m]);
        const float4 bi4 = *(const float4*)&bias[ubase];
        const float4 bf4 = *(const float4*)&bias[Hn + ubase];
        const float4 bg4 = *(const float4*)&bias[2*Hn + ubase];
        const float4 bo4 = *(const float4*)&bias[3*Hn + ubase];
        const float cold[4] = {cold4.x, cold4.y, cold4.z, cold4.w};
        const float bi[4] = {bi4.x, bi4.y, bi4.z, bi4.w};
        const float bf[4] = {bf4.x, bf4.y, bf4.z, bf4.w};
        const float bg[4] = {bg4.x, bg4.y, bg4.z, bg4.w};
        const float bo[4] = {bo4.x, bo4.y, bo4.z, bo4.w};
        float h2v[4], c2v[4];
        #pragma unroll
        for (int j = 0; j < 4; j++){
            float4 gv = *(const float4*)&Dsm[ml*68 + (tid & 3)*16 + j*4]; // i,f,g,o
            float iv = sigf(gv.x + bi[j]);
            float fv = sigf(gv.y + bf[j]);
            float gg = tanhf(gv.z + bg[j]);
            float ov = sigf(gv.w + bo[j]);
            c2v[j] = fmaf(fv, cold[j], iv*gg);
            h2v[j] = ov * tanhf(c2v[j]);
        }
        uint2 hpack;
        {
            __half2* hp = (__half2*)&hpack;
            hp[0] = make_half2(__float2half(h2v[0]), __float2half(h2v[1]));
            hp[1] = make_half2(__float2half(h2v[2]), __float2half(h2v[3]));
        }
        if (!mode && !valid) hpack = *(const uint2*)&g_hH[pin][idx0]; // bit-identical carry
        *(uint2*)&g_hH[pout][idx0] = hpack;
        __syncthreads();                       // all h writes issued
        if (tid == 0){
            __threadfence();                   // release
            atomicAdd(&g_arrive, 1u);
        }

        // ---- phase B (overlaps barrier poll): CTA-local writes + W prefetch ----
        if (!mode){
            *(float4*)&g_c[idx0] = valid ? make_float4(c2v[0], c2v[1], c2v[2], c2v[3]) : cold4;
            *(float4*)&enc_out[((size_t)m*Tn + step)*Hn + ubase] =
                valid ? make_float4(h2v[0], h2v[1], h2v[2], h2v[3])
                      : make_float4(0.f, 0.f, 0.f, 0.f);
        } else {
            *(float4*)&g_c[idx0] = make_float4(c2v[0], c2v[1], c2v[2], c2v[3]);
            *(uint2*)&g_dech16[((size_t)step*Bn + m)*Hn + ubase] = hpack;
        }
        if (it + 1 < 2*Tn){                    // next-step W prefetch, uncommitted
            const __half* Wn; int Kn;
            const int nit = it + 1;
            if (nit < Tn){ Wn = g_Wenc; Kn = KCAT; }
            else {
                int nstep = nit - Tn;
                int teach = (nstep == 0) ? 1 : tf_mask[nstep - 1];
                if (teach){ Wn = g_Wdec; Kn = KCAT; }
                else      { Wn = g_Wsum16; Kn = KHn; }
            }
            #pragma unroll
            for (int s = 0; s < 3; s++){
                const int k0 = s << 7;
                const uint32_t sb = ring_base + (uint32_t)s*STAGE_BYTES;
                #pragma unroll
                for (int i = 0; i < 4; i++){
                    int c = tid + (i << 8);
                    int r = c >> 4, q = c & 15;
                    cp16(sb + (uint32_t)((OFF_Bh + r*PITCH + (q << 3))*2),
                         Wn + (size_t)(nt*64 + r)*Kn + k0 + (q << 3));
                }
            }
        }
        if (tid == 0){
            const unsigned goal = (unsigned)(it + 1) * gridDim.x;
            while (*((volatile unsigned*)&g_arrive) < goal) {}
        }
        __syncthreads();                       // release all threads
    }
}

// ---------------------------------------------------------------------------
// Final output projection (fp16 wmma): out[b][s][:] = dech16[s][b][:]@linw16^T + b
// Grid (1024, 2): 64-row x 64-col tiles; same BK=128 ring pipeline.
// ---------------------------------------------------------------------------
__global__ __launch_bounds__(256, 1) void final_gemm16_kernel(
    const float* __restrict__ linb, float* __restrict__ out){
    extern __shared__ __align__(16) char DS[];
    __half* RINGh = (__half*)DS;
    float*  Dsm   = (float*)(DS + 3*STAGE_BYTES);    // alias of slot 3
    const uint32_t ring_base = (uint32_t)__cvta_generic_to_shared(DS);
    const int tid = threadIdx.x, wid = tid >> 5;
    const int wm = wid & 3, wn = wid >> 2;
    const int r0 = blockIdx.x << 6;                  // row tile (0..1023)
    const int n0 = blockIdx.y << 6;                  // col tile (0..1)

    auto issue = [&](int s){
        const int k0 = s << 7;
        const uint32_t sb = ring_base + (uint32_t)(s & 3)*STAGE_BYTES;
        #pragma unroll
        for (int i = 0; i < 4; i++){                 // A: 64 rows x 16 chunks
            int c = tid + (i << 8);
            int r = c >> 4, q = c & 15;
            cp16(sb + (uint32_t)((OFF_Ah + r*PITCH + (q << 3))*2),
                 g_dech16 + (size_t)(r0 + r)*Hn + k0 + (q << 3));
        }
        #pragma unroll
        for (int i = 0; i < 4; i++){                 // B: 64 rows x 16 chunks
            int c = tid + (i << 8);
            int r = c >> 4, q = c & 15;
            cp16(sb + (uint32_t)((OFF_Bh + r*PITCH + (q << 3))*2),
                 g_linw16 + (size_t)(n0 + r)*Hn + k0 + (q << 3));
        }
        asm volatile("cp.async.commit_group;\n");
    };

    wmma::fragment<wmma::accumulator,16,16,16,float> acc[2];
    wmma::fill_fragment(acc[0], 0.0f);
    wmma::fill_fragment(acc[1], 0.0f);

    issue(0); issue(1); issue(2);
    for (int s = 0; s < 8; s++){
        const int rem = 7 - s;
        if (rem >= 2)      asm volatile("cp.async.wait_group 2;\n");
        else if (rem == 1) asm volatile("cp.async.wait_group 1;\n");
        else               asm volatile("cp.async.wait_group 0;\n");
        __syncthreads();
        if (s + 3 < 8) issue(s + 3);
        const __half* SB = RINGh + (size_t)(s & 3)*(STAGE_BYTES/2);
        #pragma unroll
        for (int kcl = 0; kcl < 8; kcl++){
            wmma::fragment<wmma::matrix_a,16,16,16,__half,wmma::row_major> aH;
            wmma::fragment<wmma::matrix_b,16,16,16,__half,wmma::col_major> b0, b1;
            wmma::load_matrix_sync(aH, SB + OFF_Ah + (wm*16)*PITCH + kcl*16, PITCH);
            wmma::load_matrix_sync(b0, SB + OFF_Bh + (wn*32)*PITCH + kcl*16, PITCH);
            wmma::load_matrix_sync(b1, SB + OFF_Bh + (wn*32 + 16)*PITCH + kcl*16, PITCH);
            wmma::mma_sync(acc[0], aH, b0, acc[0]);
            wmma::mma_sync(acc[1], aH, b1, acc[1]);
        }
        __syncthreads();                       // reads done before slot reuse/D store
    }

    wmma::store_matrix_sync(&Dsm[(wm*16)*68 + wn*32 +  0], acc[0], 68, wmma::mem_row_major);
    wmma::store_matrix_sync(&Dsm[(wm*16)*68 + wn*32 + 16], acc[1], 68, wmma::mem_row_major);
    __syncthreads();

    const int ml = tid >> 2;
    const int r  = r0 + ml;
    const int s  = r >> 7;                     // time step
    const int b  = r & 127;                    // batch
    #pragma unroll
    for (int j = 0; j < 4; j++){
        const int c = (tid & 3)*16 + j*4;
        float4 v = *(const float4*)&Dsm[ml*68 + c];
        float4 lb = *(const float4*)&linb[n0 + c];
        v.x += lb.x; v.y += lb.y; v.z += lb.z; v.w += lb.w;
        *(float4*)&out[((size_t)b*Tn + s)*In + n0 + c] = v;
    }
}

// ---------------------------------------------------------------------------
// kernel_launch — 10 graph nodes. No __device__ symbol passed from host.
// Inputs: x_input, enc_Wih, enc_Whh, enc_bih, enc_bhh, dec_Wih, dec_Whh,
//         dec_bih, dec_bhh, lin_W, lin_b, lengths, tf_mask.
// Output: [outputs (B*T*I) | encoder_output (B*T*H)] float32.
// ---------------------------------------------------------------------------
extern "C" void kernel_launch(void* const* d_in, const int* in_sizes, int n_in,
                              void* d_out, int out_size){
    const float* x       = (const float*)d_in[0];
    const float* eWih    = (const float*)d_in[1];
    const float* eWhh    = (const float*)d_in[2];
    const float* ebih    = (const float*)d_in[3];
    const float* ebhh    = (const float*)d_in[4];
    const float* dWih    = (const float*)d_in[5];
    const float* dWhh    = (const float*)d_in[6];
    const float* dbih    = (const float*)d_in[7];
    const float* dbhh    = (const float*)d_in[8];
    const float* linW    = (const float*)d_in[9];
    const float* linb    = (const float*)d_in[10];
    const int*   lengths = (const int*)d_in[11];
    const int*   tfm     = (const int*)d_in[12];
    float* out = (float*)d_out;
    float* enc_out = out + (size_t)Bn*Tn*In;

    cudaFuncSetAttribute(lstm_persist_kernel,
                         cudaFuncAttributeMaxDynamicSharedMemorySize, SMEM_BYTES);
    cudaFuncSetAttribute(final_gemm16_kernel,
                         cudaFuncAttributeMaxDynamicSharedMemorySize, SMEM_BYTES);

    zero_state_kernel<<<(BHn + 255)/256, 256>>>();
    pack_w_kernel<<<(int)(((size_t)Gn*KCAT + 255)/256), 256>>>(eWhh, eWih, 0, KCAT);
    pack_w_kernel<<<(int)(((size_t)Gn*KCAT + 255)/256), 256>>>(dWhh, dWih, 1, KCAT);
    build_wsum_kernel<<<Gn, 256>>>(dWhh, dWih, linW);
    pack_w_kernel<<<(int)(((size_t)Gn*KHn + 255)/256), 256>>>((const float*)0, (const float*)0, 2, KHn);
    build_bias_kernel<<<(Gn + 255)/256, 256>>>(ebih, ebhh, dbih, dbhh, dWih, linb);
    pack_x_kernel<<<(int)(((size_t)Tn*Bn*In + 255)/256), 256>>>(x);
    pack_linw_kernel<<<(In*Hn + 255)/256, 256>>>(linW);

    lstm_persist_kernel<<<128, 256, SMEM_BYTES>>>(lengths, tfm, enc_out);

    final_gemm16_kernel<<<dim3((Tn*Bn)/64, In/64), 256, SMEM_BYTES>>>(linb, out);
}